// round 6
// baseline (speedup 1.0000x reference)
#include <cuda_runtime.h>
#include <math.h>
#include <cstdint>

#define N    3072
#define NT   1024
#define NWP  32

#define ANGLE_THR_BITS 0x3FC90FDB   // f32(pi/2)
#define FULLMASK 0xffffffffu

// Precomputed pairwise distance matrix (bit-exact ref 'dists'), 37.7MB.
__device__ float g_dmat[(size_t)N * N];

struct Smem {
    float px[N], py[N], pz[N];     // points (px reused as sort keys later)
    int   slbl[N];                 // per-point class
    int   sdl[N];                  // per-point cluster label
    float ccx[N], ccy[N], ccz[N];  // per-cluster centres
    int   ccount[N], ccls[N];      // per-cluster size / class
    int   order[N];                // scan: member list; post: sort order
    int   items[N];                // scan: unvisited packed (idx | lbl<<12); post: class lists
    int   remap[N];                // scan: posOf; post: merge remap
    unsigned char keep[N];
    float amdxy[10], amdz[10], ar2[10];
    int   clsCount[10], clsBase[11];
    int   bnc;
};

__device__ __forceinline__ float norm3_xla(float x, float y, float z) {
    float s = __fadd_rn(__fadd_rn(__fmul_rn(x, x), __fmul_rn(y, y)), __fmul_rn(z, z));
    return __fsqrt_rn(s);
}
// XLA acos lowering: 2*atan2(sqrt(1-x*x), 1+x); pi at x==-1. Same libdevice atan2f
// as the reference -> bit-identical.
__device__ __forceinline__ float acos_xla(float x) {
    float s = __fsqrt_rn(__fsub_rn(1.0f, __fmul_rn(x, x)));
    float r = 2.0f * atan2f(s, __fadd_rn(1.0f, x));
    if (x == -1.0f) r = __int_as_float(0x40490FDB);
    return r;
}
__device__ __forceinline__ unsigned ford(float f) {          // float -> ordered uint
    unsigned u = __float_as_uint(f);
    return (u & 0x80000000u) ? ~u : (u | 0x80000000u);
}
__device__ __forceinline__ float ford_inv(unsigned o) {
    unsigned u = (o & 0x80000000u) ? (o ^ 0x80000000u) : ~o;
    return __uint_as_float(u);
}

#define INF_F  (__int_as_float(0x7f800000))
#define NINF_F (__int_as_float(0xff800000))

// Largest float x with fl(x/Dn) <= qT.  Analytic double guess + ground-truth probes.
__device__ __forceinline__ float upper_x_for_q(float qT, float Dn) {
    double B = ((double)qT + (double)nextafterf(qT, INF_F)) * 0.5;
    float x = __double2float_rd(B * (double)Dn);
    for (int it = 0; it < 8; ++it) {
        float nx = nextafterf(x, INF_F);
        if (__fdiv_rn(nx, Dn) <= qT) x = nx; else break;
    }
    for (int it = 0; it < 8; ++it) {
        if (__fdiv_rn(x, Dn) > qT) x = nextafterf(x, NINF_F); else break;
    }
    return x;
}
// Largest float q with fl(q + 1.0f) <= cB.
__device__ __forceinline__ float upper_q_for_cost(float cB) {
    float q = __double2float_rd((double)cB - 1.0);
    for (int it = 0; it < 8; ++it) {
        float nq = nextafterf(q, INF_F);
        if (__fadd_rn(nq, 1.0f) <= cB) q = nq; else break;
    }
    for (int it = 0; it < 8; ++it) {
        if (__fadd_rn(q, 1.0f) > cB) q = nextafterf(q, NINF_F); else break;
    }
    return q;
}
// Largest float d with fl(d - dmin) <= xhi.
__device__ __forceinline__ float upper_d_for_x(float xhi, float dmin) {
    float d = __double2float_rd((double)dmin + (double)xhi);
    for (int it = 0; it < 8; ++it) {
        float nd = nextafterf(d, INF_F);
        if (__fsub_rn(nd, dmin) <= xhi) d = nd; else break;
    }
    for (int it = 0; it < 8; ++it) {
        if (__fsub_rn(d, dmin) > xhi) d = nextafterf(d, NINF_F); else break;
    }
    return d;
}

__global__ void dist_kernel(const float* __restrict__ pts) {
    int i = blockIdx.x;
    float ax = pts[3*i], ay = pts[3*i+1], az = pts[3*i+2];
    float* row = g_dmat + (size_t)i * N;
    for (int j = threadIdx.x; j < N; j += blockDim.x) {
        float dx = __fsub_rn(pts[3*j],   ax);
        float dy = __fsub_rn(pts[3*j+1], ay);
        float dz = __fsub_rn(pts[3*j+2], az);
        row[j] = norm3_xla(dx, dy, dz);
    }
}

__global__ void __launch_bounds__(NT, 1)
frustum_cluster_kernel(const float* __restrict__ pts,
                       const int*   __restrict__ lbl,
                       const float* __restrict__ anchors,
                       float* __restrict__ out)
{
    extern __shared__ char raw[];
    Smem& S = *reinterpret_cast<Smem*>(raw);

    const int tid  = threadIdx.x;
    const int wid  = tid >> 5;
    const int lane = tid & 31;
    const float THR = __int_as_float(ANGLE_THR_BITS);

    // ---------------- init (all threads) ----------------
    for (int j = tid; j < N; j += NT) {
        S.px[j]   = pts[3*j + 0];
        S.py[j]   = pts[3*j + 1];
        S.pz[j]   = pts[3*j + 2];
        S.slbl[j] = lbl[j];
        if (j >= 1) {
            S.items[j - 1] = j | (lbl[j] << 12);
            S.remap[j]     = j - 1;
        }
    }
    if (tid < 10) {
        float l = anchors[tid*3+0], w = anchors[tid*3+1], h = anchors[tid*3+2];
        S.amdxy[tid] = fmaxf(l, w);
        S.amdz[tid]  = h;
        S.ar2[tid]   = __fdiv_rn(norm3_xla(l, w, h), 2.0f);
    }
    if (tid == 0) {
        S.sdl[0]   = 0;
        S.ccls[0]  = lbl[0];
        S.order[0] = 0;
    }
    __syncthreads();

    // ================= single-warp greedy scan (warp 0 only) =================
    if (wid == 0) {
        // angle-threshold precompute (warp-redundant): largest x with acos >= THR
        unsigned lo = ford(-1.0f), hi = ford(1.0f);
        while (hi - lo > 1u) {
            unsigned mid = lo + ((hi - lo) >> 1);
            if (acos_xla(ford_inv(mid)) >= THR) lo = mid; else hi = mid;
        }
        const float    bval  = ford_inv(lo);
        const unsigned ordb  = lo;
        const int      flag0 = (acos_xla(0.0f) < THR) ? 1 : 0;

        int m = N - 1, cur = 0, cls = S.slbl[0];
        int lab = 0, cnt = 1, mcnt = 1;
        float  cx = S.px[0], cy = S.py[0], cz = S.pz[0];
        float  pn = norm3_xla(cx, cy, cz);
        double sx = (double)cx, sy = (double)cy, sz = (double)cz;

        while (m > 0) {
            const float* __restrict__ drow = g_dmat + (size_t)cur * N;

            // ---- angle pass over current cluster members ----
            unsigned xmb = 0xFFFFFFFFu;   // ford-mapped min
            for (int i = lane; i < mcnt; i += 32) {
                int j = S.order[i];
                float dx = __fsub_rn(S.px[j], cx);
                float dy = __fsub_rn(S.py[j], cy);
                float dz = __fsub_rn(S.pz[j], cz);
                float dd = __ldg(drow + j);
                float dt = -(__fadd_rn(__fadd_rn(__fmul_rn(cx,dx), __fmul_rn(cy,dy)),
                                       __fmul_rn(cz,dz)));
                float den = __fadd_rn(__fmul_rn(pn, dd), 1e-8f);
                xmb = min(xmb, ford(__fdiv_rn(dt, den)));
            }
            xmb = __reduce_min_sync(FULLMASK, xmb);
            float xc = fminf(fmaxf(ford_inv(xmb), -1.0f), 1.0f);
            bool angflag;
            if (xc == 0.0f) {
                angflag = (flag0 != 0);
            } else {
                long dlt = (long)ford(xc) - (long)ordb;
                if (dlt > -65536 && dlt < 65536) angflag = (acos_xla(xc) < THR);
                else                             angflag = (xc > bval);
            }

            // ---- pass 1: value reductions over unvisited ----
            unsigned minA = 0xFFFFFFFFu, minB = 0xFFFFFFFFu, maxAll = 0u;
            for (int pos = lane; pos < m; pos += 32) {
                int pk = S.items[pos];
                unsigned db = __float_as_uint(__ldg(drow + (pk & 0xFFF)));
                if ((pk >> 12) == cls) minA = min(minA, db);
                else                   minB = min(minB, db);
                maxAll = max(maxAll, db);
            }
            minA   = __reduce_min_sync(FULLMASK, minA);
            minB   = __reduce_min_sync(FULLMASK, minB);
            maxAll = __reduce_max_sync(FULLMASK, maxAll);

            bool hasA = (minA != 0xFFFFFFFFu), hasB = (minB != 0xFFFFFFFFu);
            unsigned minAll = min(minA, minB);
            float dmin = __uint_as_float(minAll);
            float dmax = __uint_as_float(maxAll);
            float Dn   = __fadd_rn(__fsub_rn(dmax, dmin), 1e-8f);

            // ---- warp-redundant boundary math (exact via probes) ----
            float costA = INF_F, cB = INF_F, qA = 0.f, qB = 0.f;
            if (hasA) {
                qA = __fdiv_rn(__fsub_rn(__uint_as_float(minA), dmin), Dn);
                costA = qA;   // + 0.0f exact
            }
            if (hasB) {
                qB = __fdiv_rn(__fsub_rn(__uint_as_float(minB), dmin), Dn);
                cB = __fadd_rn(qB, 1.0f);
            }
            float cstar = fminf(costA, cB);
            float thrA = NINF_F, thrB = NINF_F;
            if (hasA && costA == cstar)
                thrA = upper_d_for_x(upper_x_for_q(qA, Dn), dmin);
            if (hasB && cB == cstar)
                thrB = upper_d_for_x(upper_x_for_q(upper_q_for_cost(cB), Dn), dmin);

            // ---- pass 2: min index among cost-minimizers ----
            unsigned best = 0xFFFFFFFFu;
            for (int pos = lane; pos < m; pos += 32) {
                int pk = S.items[pos];
                int j  = pk & 0xFFF;
                float d = __ldg(drow + j);
                float thr = ((pk >> 12) == cls) ? thrA : thrB;
                if (d <= thr) best = min(best, (unsigned)j);
            }
            int sel = (int)__reduce_min_sync(FULLMASK, best);

            // ---- remove sel from unvisited (warp-redundant same-value stores) --
            {
                int p = S.remap[sel];
                int lastpk = S.items[m - 1];
                S.items[p] = lastpk;
                S.remap[lastpk & 0xFFF] = p;
                m--;
            }

            // ---- cluster decision (warp-redundant) ----
            float cix = S.px[sel], ciy = S.py[sel], ciz = S.pz[sel];
            int   lci = S.slbl[sel];
            float dx = __fsub_rn(cx, cix);
            float dy = __fsub_rn(cy, ciy);
            float dz = __fsub_rn(cz, ciz);
            float dn = norm3_xla(dx, dy, dz);
            float cf = (float)cnt;
            float gx = __fdiv_rn((float)sx, cf);
            float gy = __fdiv_rn((float)sy, cf);
            float gz = __fdiv_rn((float)sz, cf);
            float en = norm3_xla(__fsub_rn(gx, cix), __fsub_rn(gy, ciy),
                                 __fsub_rn(gz, ciz));
            float a0 = S.amdxy[cls], a2 = S.amdz[cls], r2 = S.ar2[cls];
            bool newc = (fabsf(dx) > a0) | (fabsf(dy) > a0) | (fabsf(dz) > a2) |
                        angflag | (lci != cls) | (dn > r2) | (en > r2);
            if (newc) {
                S.ccx[lab] = gx; S.ccy[lab] = gy; S.ccz[lab] = gz;
                S.ccount[lab] = cnt;
                lab += 1;
                sx = (double)cix; sy = (double)ciy; sz = (double)ciz; cnt = 1;
                S.ccls[lab] = lci;
                mcnt = 0;
            } else {
                sx += (double)cix; sy += (double)ciy; sz += (double)ciz; cnt += 1;
            }
            S.order[mcnt] = sel; mcnt += 1;
            S.sdl[sel] = lab;
            cur = sel; cls = lci;
            cx = cix; cy = ciy; cz = ciz;
            pn = norm3_xla(cx, cy, cz);
        }
        S.bnc = lab;   // num_clusters (exclusive), same-value store by all lanes
    }
    __syncthreads();

    const int nc = S.bnc;

    // ---------------- stable descending sort by count (bitonic, 4096 keys) -----
    unsigned* skey = reinterpret_cast<unsigned*>(S.px);
    for (int i = tid; i < 4096; i += NT) {
        unsigned key = 0;
        if (i < nc) key = ((unsigned)S.ccount[i] << 12) | (4095u - (unsigned)i);
        skey[i] = key;
    }
    for (int i = tid; i < N; i += NT) { S.remap[i] = i; S.keep[i] = 1; }
    __syncthreads();

    for (int k = 2; k <= 4096; k <<= 1) {
        for (int j = k >> 1; j > 0; j >>= 1) {
#pragma unroll
            for (int e = 0; e < 4; ++e) {
                int i = tid + e * NT;
                int ixj = i ^ j;
                if (ixj > i) {
                    unsigned a2 = skey[i], b2 = skey[ixj];
                    bool descBlock = ((i & k) == 0);
                    if (descBlock ? (a2 < b2) : (a2 > b2)) { skey[i] = b2; skey[ixj] = a2; }
                }
            }
            __syncthreads();
        }
    }
    for (int i = tid; i < N; i += NT)
        if (i < nc) S.order[i] = 4095 - (int)(skey[i] & 4095u);
    __syncthreads();

    // ---------------- group order-positions by cluster class ----------
    if (wid < 10) {
        int c = wid, total = 0;
        int limit = (nc + 31) & ~31;
        for (int s = lane; s < limit; s += 32) {
            bool mm = (s < nc) && (S.ccls[S.order[s]] == c);
            unsigned bal = __ballot_sync(FULLMASK, mm);
            total += __popc(bal);
        }
        if (lane == 0) S.clsCount[c] = total;
    }
    __syncthreads();
    if (tid == 0) {
        int acc = 0;
        for (int c = 0; c < 10; ++c) { S.clsBase[c] = acc; acc += S.clsCount[c]; }
        S.clsBase[10] = acc;
    }
    __syncthreads();
    if (wid < 10) {
        int c = wid;
        int pos = S.clsBase[c];
        int limit = (nc + 31) & ~31;
        for (int s = lane; s < limit; s += 32) {
            bool mm = (s < nc) && (S.ccls[S.order[s]] == c);
            unsigned bal = __ballot_sync(FULLMASK, mm);
            if (mm) {
                int off = __popc(bal & ((1u << lane) - 1u));
                S.items[pos + off] = s;
            }
            pos += __popc(bal);
        }
    }
    __syncthreads();

    // ---------------- merge: independent per-class sequential chains ----------
    if (wid < 10) {
        int c    = wid;
        int base = S.clsBase[c];
        int len  = S.clsBase[c + 1] - base;
        float r2c = S.ar2[c];
        for (int t = 0; t < len; ++t) {
            __syncwarp();
            int ipos = S.items[base + t];
            if (!S.keep[ipos]) continue;
            int idx = S.order[ipos];
            float ax = S.ccx[idx], ay = S.ccy[idx], az = S.ccz[idx];
            for (int s = t + 1 + lane; s < len; s += 32) {
                int jpos = S.items[base + s];
                if (S.keep[jpos]) {
                    int jidx = S.order[jpos];
                    float dd = norm3_xla(__fsub_rn(S.ccx[jidx], ax),
                                         __fsub_rn(S.ccy[jidx], ay),
                                         __fsub_rn(S.ccz[jidx], az));
                    if (dd < r2c) {
                        S.keep[jpos]  = 0;
                        S.remap[jidx] = idx;
                    }
                }
            }
        }
    }
    __syncthreads();

    // ---------------- output (float32) ----------------
    for (int i = tid; i < N; i += NT)
        out[i] = (float)S.remap[S.sdl[i]];
}

extern "C" void kernel_launch(void* const* d_in, const int* in_sizes, int n_in,
                              void* d_out, int out_size)
{
    const float* pts     = nullptr;
    const int*   lbls    = nullptr;
    const float* anchors = nullptr;
    for (int i = 0; i < n_in; ++i) {
        if      (in_sizes[i] == N * 3) pts     = (const float*)d_in[i];
        else if (in_sizes[i] == N)     lbls    = (const int*)  d_in[i];
        else if (in_sizes[i] == 30)    anchors = (const float*)d_in[i];
    }
    if (!pts)     pts     = (const float*)d_in[0];
    if (!lbls)    lbls    = (const int*)  d_in[1];
    if (!anchors) anchors = (const float*)d_in[2];

    float* out = (float*)d_out;
    (void)out_size;

    static bool attr_done = false;
    if (!attr_done) {
        cudaFuncSetAttribute(frustum_cluster_kernel,
                             cudaFuncAttributeMaxDynamicSharedMemorySize,
                             (int)sizeof(Smem));
        attr_done = true;
    }
    dist_kernel<<<N, 256>>>(pts);
    frustum_cluster_kernel<<<1, NT, sizeof(Smem)>>>(pts, lbls, anchors, out);
}

// round 7
// speedup vs baseline: 1.7584x; 1.7584x over previous
#include <cuda_runtime.h>
#include <math.h>
#include <cstdint>

#define N    3072
#define NT   256
#define NWP  8
#define PER  12      // N / NT

#define ANGLE_THR_BITS 0x3FC90FDB   // f32(pi/2)
#define FULLMASK 0xffffffffu
#define INF_F  (__int_as_float(0x7f800000))
#define NINF_F (__int_as_float(0xff800000))

struct Smem {
    float px[N], py[N], pz[N];     // points (px reused as sort keys later)
    int   slbl[N];                 // per-point class
    int   sdl[N];                  // per-point cluster label
    float ccx[N], ccy[N], ccz[N];  // per-cluster centres
    int   ccount[N], ccls[N];      // per-cluster size / class
    int   order[N];                // post: sort order
    int   items[N];                // post: class lists
    int   remap[N];                // post: merge remap
    unsigned char keep[N];
    unsigned pminA[NWP], pminB[NWP], pmax[NWP], pxm[NWP], psel[NWP];
    float amdxy[10], amdz[10], ar2[10];
    int   clsCount[10], clsBase[11];
    int   bnc;
    float bval; unsigned ordb; int flag0;   // angle threshold data
};

__device__ __forceinline__ float norm3_xla(float x, float y, float z) {
    float s = __fadd_rn(__fadd_rn(__fmul_rn(x, x), __fmul_rn(y, y)), __fmul_rn(z, z));
    return __fsqrt_rn(s);
}
// XLA acos lowering: 2*atan2(sqrt(1-x*x), 1+x); pi at x==-1. Same libdevice atan2f
// as the reference -> bit-identical.
__device__ __forceinline__ float acos_xla(float x) {
    float s = __fsqrt_rn(__fsub_rn(1.0f, __fmul_rn(x, x)));
    float r = 2.0f * atan2f(s, __fadd_rn(1.0f, x));
    if (x == -1.0f) r = __int_as_float(0x40490FDB);
    return r;
}
__device__ __forceinline__ unsigned ford(float f) {
    unsigned u = __float_as_uint(f);
    return (u & 0x80000000u) ? ~u : (u | 0x80000000u);
}
__device__ __forceinline__ float ford_inv(unsigned o) {
    unsigned u = (o & 0x80000000u) ? (o ^ 0x80000000u) : ~o;
    return __uint_as_float(u);
}

// Largest float x with fl(x/Dn) <= qT (ground-truth probes around analytic guess).
__device__ __forceinline__ float upper_x_for_q(float qT, float Dn) {
    double B = ((double)qT + (double)nextafterf(qT, INF_F)) * 0.5;
    float x = __double2float_rd(B * (double)Dn);
    for (int it = 0; it < 8; ++it) {
        float nx = nextafterf(x, INF_F);
        if (__fdiv_rn(nx, Dn) <= qT) x = nx; else break;
    }
    for (int it = 0; it < 8; ++it) {
        if (__fdiv_rn(x, Dn) > qT) x = nextafterf(x, NINF_F); else break;
    }
    return x;
}
// Largest float q with fl(q + 1.0f) <= cB.
__device__ __forceinline__ float upper_q_for_cost(float cB) {
    float q = __double2float_rd((double)cB - 1.0);
    for (int it = 0; it < 8; ++it) {
        float nq = nextafterf(q, INF_F);
        if (__fadd_rn(nq, 1.0f) <= cB) q = nq; else break;
    }
    for (int it = 0; it < 8; ++it) {
        if (__fadd_rn(q, 1.0f) > cB) q = nextafterf(q, NINF_F); else break;
    }
    return q;
}
// Largest float d with fl(d - dmin) <= xhi.
__device__ __forceinline__ float upper_d_for_x(float xhi, float dmin) {
    float d = __double2float_rd((double)dmin + (double)xhi);
    for (int it = 0; it < 8; ++it) {
        float nd = nextafterf(d, INF_F);
        if (__fsub_rn(nd, dmin) <= xhi) d = nd; else break;
    }
    for (int it = 0; it < 8; ++it) {
        if (__fsub_rn(d, dmin) > xhi) d = nextafterf(d, NINF_F); else break;
    }
    return d;
}

__global__ void __launch_bounds__(NT, 1)
frustum_cluster_kernel(const float* __restrict__ pts,
                       const int*   __restrict__ lbl,
                       const float* __restrict__ anchors,
                       float* __restrict__ out)
{
    extern __shared__ char raw[];
    Smem& S = *reinterpret_cast<Smem*>(raw);

    const int tid  = threadIdx.x;
    const int wid  = tid >> 5;
    const int lane = tid & 31;
    const float THR = __int_as_float(ANGLE_THR_BITS);

    // ---------------- init ----------------
    for (int j = tid; j < N; j += NT) {
        S.px[j]   = pts[3*j + 0];
        S.py[j]   = pts[3*j + 1];
        S.pz[j]   = pts[3*j + 2];
        S.slbl[j] = lbl[j];
    }
    if (tid < 10) {
        float l = anchors[tid*3+0], w = anchors[tid*3+1], h = anchors[tid*3+2];
        S.amdxy[tid] = fmaxf(l, w);
        S.amdz[tid]  = h;
        S.ar2[tid]   = __fdiv_rn(norm3_xla(l, w, h), 2.0f);
    }
    if (tid == 0) {
        S.sdl[0]  = 0;
        S.ccls[0] = lbl[0];
        // binary search for angle threshold: largest x with acos_xla(x) >= THR
        unsigned lo = ford(-1.0f), hi = ford(1.0f);
        while (hi - lo > 1u) {
            unsigned mid = lo + ((hi - lo) >> 1);
            if (acos_xla(ford_inv(mid)) >= THR) lo = mid; else hi = mid;
        }
        S.bval  = ford_inv(lo);
        S.ordb  = lo;
        S.flag0 = (acos_xla(0.0f) < THR) ? 1 : 0;
    }
    __syncthreads();

    // ---- per-thread register caches (slot k <-> point j = tid + k*NT) ----
    float mx[PER], my_[PER], mz_[PER], dreg[PER];
    int   ml[PER], mydl[PER];
    unsigned mvbits = 0;              // visited bitmask over slots
#pragma unroll
    for (int k = 0; k < PER; ++k) {
        int j = tid + (k << 8);
        mx[k] = S.px[j]; my_[k] = S.py[j]; mz_[k] = S.pz[j];
        ml[k] = S.slbl[j];
        mydl[k] = (j == 0) ? 0 : -1;
        if (j == 0) mvbits |= 1u;     // only thread 0 slot 0
    }

    const float    bval  = S.bval;
    const unsigned ordb  = S.ordb;
    const int      flag0 = S.flag0;

    // ---- fully-redundant scan state (identical in every thread) ----
    int cur = 0, cls = S.slbl[0], curlab = 0;
    int lab = 0, cnt = 1;
    float  cx = S.px[0], cy = S.py[0], cz = S.pz[0];
    float  pn = norm3_xla(cx, cy, cz);
    double sx = (double)cx, sy = (double)cy, sz = (double)cz;

    // ---------------- greedy scan: N-1 steps, 2 barriers each ----------------
    for (int step = 0; step < N - 1; ++step) {
        // pass 1: compute dists; class-split min + max over unvisited;
        //         ford-min of cos-arg over current-cluster members.
        unsigned minA = 0xFFFFFFFFu, minB = 0xFFFFFFFFu, maxAll = 0u, xmb = 0xFFFFFFFFu;
#pragma unroll
        for (int k = 0; k < PER; ++k) {
            float dx = __fsub_rn(mx[k],  cx);
            float dy = __fsub_rn(my_[k], cy);
            float dz = __fsub_rn(mz_[k], cz);
            float d  = norm3_xla(dx, dy, dz);
            dreg[k] = d;
            if (!(mvbits & (1u << k))) {
                unsigned db = __float_as_uint(d);
                if (ml[k] == cls) minA = min(minA, db);
                else              minB = min(minB, db);
                maxAll = max(maxAll, db);
            } else if (mydl[k] == curlab) {
                float dt = -(__fadd_rn(__fadd_rn(__fmul_rn(cx,dx), __fmul_rn(cy,dy)),
                                       __fmul_rn(cz,dz)));
                float den = __fadd_rn(__fmul_rn(pn, d), 1e-8f);
                xmb = min(xmb, ford(__fdiv_rn(dt, den)));
            }
        }
        minA   = __reduce_min_sync(FULLMASK, minA);
        minB   = __reduce_min_sync(FULLMASK, minB);
        maxAll = __reduce_max_sync(FULLMASK, maxAll);
        xmb    = __reduce_min_sync(FULLMASK, xmb);
        if (lane == 0) {
            S.pminA[wid] = minA; S.pminB[wid] = minB;
            S.pmax[wid]  = maxAll; S.pxm[wid] = xmb;
        }
        __syncthreads();                                   // barrier 1

        // every warp re-reduces the 8 partials (this IS the broadcast)
        {
            unsigned a = (lane < NWP) ? S.pminA[lane] : 0xFFFFFFFFu;
            unsigned b = (lane < NWP) ? S.pminB[lane] : 0xFFFFFFFFu;
            unsigned c = (lane < NWP) ? S.pmax[lane]  : 0u;
            unsigned x = (lane < NWP) ? S.pxm[lane]   : 0xFFFFFFFFu;
            minA   = __reduce_min_sync(FULLMASK, a);
            minB   = __reduce_min_sync(FULLMASK, b);
            maxAll = __reduce_max_sync(FULLMASK, c);
            xmb    = __reduce_min_sync(FULLMASK, x);
        }

        bool hasA = (minA != 0xFFFFFFFFu), hasB = (minB != 0xFFFFFFFFu);
        float dmin = __uint_as_float(min(minA, minB));
        float dmax = __uint_as_float(maxAll);
        float Dn   = __fadd_rn(__fsub_rn(dmax, dmin), 1e-8f);

        // angle verdict (redundant in all threads)
        float xc = fminf(fmaxf(ford_inv(xmb), -1.0f), 1.0f);
        bool angflag;
        if (xc == 0.0f) {
            angflag = (flag0 != 0);
        } else {
            long dlt = (long)ford(xc) - (long)ordb;
            if (dlt > -65536 && dlt < 65536) angflag = (acos_xla(xc) < THR);
            else                             angflag = (xc > bval);
        }

        // exact selection thresholds (redundant)
        float thrA = NINF_F, thrB = NINF_F;
        {
            float costA = INF_F, cB = INF_F, qA = 0.f, qB = 0.f;
            if (hasA) {
                qA = __fdiv_rn(__fsub_rn(__uint_as_float(minA), dmin), Dn);
                costA = qA;
            }
            if (hasB) {
                qB = __fdiv_rn(__fsub_rn(__uint_as_float(minB), dmin), Dn);
                cB = __fadd_rn(qB, 1.0f);
            }
            float cstar = fminf(costA, cB);
            if (hasA && costA == cstar)
                thrA = upper_d_for_x(upper_x_for_q(qA, Dn), dmin);
            if (hasB && cB == cstar)
                thrB = upper_d_for_x(upper_x_for_q(upper_q_for_cost(cB), Dn), dmin);
        }

        // pass 2: min index among cost-minimizers
        unsigned best = 0xFFFFFFFFu;
#pragma unroll
        for (int k = 0; k < PER; ++k) {
            if (!(mvbits & (1u << k))) {
                float thr = (ml[k] == cls) ? thrA : thrB;
                if (dreg[k] <= thr) best = min(best, (unsigned)(tid + (k << 8)));
            }
        }
        best = __reduce_min_sync(FULLMASK, best);
        if (lane == 0) S.psel[wid] = best;
        __syncthreads();                                   // barrier 2
        {
            unsigned v = (lane < NWP) ? S.psel[lane] : 0xFFFFFFFFu;
            best = __reduce_min_sync(FULLMASK, v);
        }
        int sel = (int)best;

        // ---- decision (fully redundant; identical in every thread) ----
        float cix = S.px[sel], ciy = S.py[sel], ciz = S.pz[sel];
        int   lci = S.slbl[sel];
        float ddx = __fsub_rn(cx, cix);
        float ddy = __fsub_rn(cy, ciy);
        float ddz = __fsub_rn(cz, ciz);
        float dn = norm3_xla(ddx, ddy, ddz);
        float cf = (float)cnt;
        float gx = __fdiv_rn((float)sx, cf);
        float gy = __fdiv_rn((float)sy, cf);
        float gz = __fdiv_rn((float)sz, cf);
        float en = norm3_xla(__fsub_rn(gx, cix), __fsub_rn(gy, ciy),
                             __fsub_rn(gz, ciz));
        float a0 = S.amdxy[cls], a2 = S.amdz[cls], r2 = S.ar2[cls];
        bool newc = (fabsf(ddx) > a0) | (fabsf(ddy) > a0) | (fabsf(ddz) > a2) |
                    angflag | (lci != cls) | (dn > r2) | (en > r2);
        if (newc) {
            S.ccx[lab] = gx; S.ccy[lab] = gy; S.ccz[lab] = gz;   // same-value stores
            S.ccount[lab] = cnt;
            lab += 1;
            sx = (double)cix; sy = (double)ciy; sz = (double)ciz; cnt = 1;
            S.ccls[lab] = lci;
        } else {
            sx += (double)cix; sy += (double)ciy; sz += (double)ciz; cnt += 1;
        }
        S.sdl[sel] = lab;                                        // same-value store

        // mark sel visited in its owner thread's registers (unrolled, no spills)
#pragma unroll
        for (int k = 0; k < PER; ++k) {
            if (tid + (k << 8) == sel) { mvbits |= (1u << k); mydl[k] = lab; }
        }

        cur = sel; cls = lci; curlab = lab;
        cx = cix; cy = ciy; cz = ciz;
        pn = norm3_xla(cx, cy, cz);
        (void)cur;
    }

    if (tid == 0) S.bnc = lab;   // num_clusters (exclusive)
    __syncthreads();

    const int nc = S.bnc;

    // ---------------- stable descending sort by count (bitonic, 4096 keys) -----
    unsigned* skey = reinterpret_cast<unsigned*>(S.px);
    for (int i = tid; i < 4096; i += NT) {
        unsigned key = 0;
        if (i < nc) key = ((unsigned)S.ccount[i] << 12) | (4095u - (unsigned)i);
        skey[i] = key;
    }
    for (int i = tid; i < N; i += NT) { S.remap[i] = i; S.keep[i] = 1; }
    __syncthreads();

    for (int k = 2; k <= 4096; k <<= 1) {
        for (int j = k >> 1; j > 0; j >>= 1) {
#pragma unroll
            for (int e = 0; e < 16; ++e) {
                int i = tid + e * NT;
                int ixj = i ^ j;
                if (ixj > i) {
                    unsigned a2 = skey[i], b2 = skey[ixj];
                    bool descBlock = ((i & k) == 0);
                    if (descBlock ? (a2 < b2) : (a2 > b2)) { skey[i] = b2; skey[ixj] = a2; }
                }
            }
            __syncthreads();
        }
    }
    for (int i = tid; i < N; i += NT)
        if (i < nc) S.order[i] = 4095 - (int)(skey[i] & 4095u);
    __syncthreads();

    // ---------------- group order-positions by cluster class ----------
    for (int c = wid; c < 10; c += NWP) {
        int total = 0;
        int limit = (nc + 31) & ~31;
        for (int s = lane; s < limit; s += 32) {
            bool mm = (s < nc) && (S.ccls[S.order[s]] == c);
            unsigned bal = __ballot_sync(FULLMASK, mm);
            total += __popc(bal);
        }
        if (lane == 0) S.clsCount[c] = total;
    }
    __syncthreads();
    if (tid == 0) {
        int acc = 0;
        for (int c = 0; c < 10; ++c) { S.clsBase[c] = acc; acc += S.clsCount[c]; }
        S.clsBase[10] = acc;
    }
    __syncthreads();
    for (int c = wid; c < 10; c += NWP) {
        int pos = S.clsBase[c];
        int limit = (nc + 31) & ~31;
        for (int s = lane; s < limit; s += 32) {
            bool mm = (s < nc) && (S.ccls[S.order[s]] == c);
            unsigned bal = __ballot_sync(FULLMASK, mm);
            if (mm) {
                int off = __popc(bal & ((1u << lane) - 1u));
                S.items[pos + off] = s;
            }
            pos += __popc(bal);
        }
    }
    __syncthreads();

    // ---------------- merge: independent per-class sequential chains ----------
    for (int c = wid; c < 10; c += NWP) {
        int base = S.clsBase[c];
        int len  = S.clsBase[c + 1] - base;
        float r2c = S.ar2[c];
        for (int t = 0; t < len; ++t) {
            __syncwarp();
            int ipos = S.items[base + t];
            if (!S.keep[ipos]) continue;
            int idx = S.order[ipos];
            float ax = S.ccx[idx], ay = S.ccy[idx], az = S.ccz[idx];
            for (int s = t + 1 + lane; s < len; s += 32) {
                int jpos = S.items[base + s];
                if (S.keep[jpos]) {
                    int jidx = S.order[jpos];
                    float dd = norm3_xla(__fsub_rn(S.ccx[jidx], ax),
                                         __fsub_rn(S.ccy[jidx], ay),
                                         __fsub_rn(S.ccz[jidx], az));
                    if (dd < r2c) {
                        S.keep[jpos]  = 0;
                        S.remap[jidx] = idx;
                    }
                }
            }
        }
    }
    __syncthreads();

    // ---------------- output (float32) ----------------
    for (int i = tid; i < N; i += NT)
        out[i] = (float)S.remap[S.sdl[i]];
}

extern "C" void kernel_launch(void* const* d_in, const int* in_sizes, int n_in,
                              void* d_out, int out_size)
{
    const float* pts     = nullptr;
    const int*   lbls    = nullptr;
    const float* anchors = nullptr;
    for (int i = 0; i < n_in; ++i) {
        if      (in_sizes[i] == N * 3) pts     = (const float*)d_in[i];
        else if (in_sizes[i] == N)     lbls    = (const int*)  d_in[i];
        else if (in_sizes[i] == 30)    anchors = (const float*)d_in[i];
    }
    if (!pts)     pts     = (const float*)d_in[0];
    if (!lbls)    lbls    = (const int*)  d_in[1];
    if (!anchors) anchors = (const float*)d_in[2];

    float* out = (float*)d_out;
    (void)out_size;

    static bool attr_done = false;
    if (!attr_done) {
        cudaFuncSetAttribute(frustum_cluster_kernel,
                             cudaFuncAttributeMaxDynamicSharedMemorySize,
                             (int)sizeof(Smem));
        attr_done = true;
    }
    frustum_cluster_kernel<<<1, NT, sizeof(Smem)>>>(pts, lbls, anchors, out);
}

// round 8
// speedup vs baseline: 1.9131x; 1.0880x over previous
#include <cuda_runtime.h>
#include <math.h>
#include <cstdint>

#define N    3072
#define NT   512
#define NWP  16
#define PER  6       // N / NT

#define ANGLE_THR_BITS 0x3FC90FDB   // f32(pi/2)
#define FULLMASK 0xffffffffu
#define INF_F  (__int_as_float(0x7f800000))
#define NINF_F (__int_as_float(0xff800000))

// Precomputed pairwise distance matrix (bit-exact ref 'dists'), 37.7MB (fits L2).
__device__ float g_dmat[(size_t)N * N];

struct Smem {
    float px[N], py[N], pz[N];     // points (px reused as sort keys later)
    int   slbl[N];                 // per-point class
    int   sdl[N];                  // per-point cluster label
    float ccx[N], ccy[N], ccz[N];  // per-cluster centres
    int   ccount[N], ccls[N];      // per-cluster size / class
    int   order[N];                // post: sort order
    int   items[N];                // post: class lists
    int   remap[N];                // post: merge remap
    unsigned char keep[N];
    unsigned pminA[NWP], pminB[NWP], pmax[NWP], pxm[NWP], psel[NWP];
    float amdxy[10], amdz[10], ar2[10];
    int   clsCount[10], clsBase[11];
    int   bnc, bnew;
    float bval; unsigned ordb; int flag0;   // angle threshold data
};

__device__ __forceinline__ float norm3_xla(float x, float y, float z) {
    float s = __fadd_rn(__fadd_rn(__fmul_rn(x, x), __fmul_rn(y, y)), __fmul_rn(z, z));
    return __fsqrt_rn(s);
}
// XLA acos lowering: 2*atan2(sqrt(1-x*x), 1+x); pi at x==-1. Same libdevice atan2f
// as the reference -> bit-identical.
__device__ __forceinline__ float acos_xla(float x) {
    float s = __fsqrt_rn(__fsub_rn(1.0f, __fmul_rn(x, x)));
    float r = 2.0f * atan2f(s, __fadd_rn(1.0f, x));
    if (x == -1.0f) r = __int_as_float(0x40490FDB);
    return r;
}
__device__ __forceinline__ unsigned ford(float f) {
    unsigned u = __float_as_uint(f);
    return (u & 0x80000000u) ? ~u : (u | 0x80000000u);
}
__device__ __forceinline__ float ford_inv(unsigned o) {
    unsigned u = (o & 0x80000000u) ? (o ^ 0x80000000u) : ~o;
    return __uint_as_float(u);
}

__global__ void dist_kernel(const float* __restrict__ pts) {
    int i = blockIdx.x;
    float ax = pts[3*i], ay = pts[3*i+1], az = pts[3*i+2];
    float* row = g_dmat + (size_t)i * N;
    for (int j = threadIdx.x; j < N; j += blockDim.x) {
        float dx = __fsub_rn(pts[3*j],   ax);
        float dy = __fsub_rn(pts[3*j+1], ay);
        float dz = __fsub_rn(pts[3*j+2], az);
        row[j] = norm3_xla(dx, dy, dz);
    }
}

__global__ void __launch_bounds__(NT, 1)
frustum_cluster_kernel(const float* __restrict__ pts,
                       const int*   __restrict__ lbl,
                       const float* __restrict__ anchors,
                       float* __restrict__ out)
{
    extern __shared__ char raw[];
    Smem& S = *reinterpret_cast<Smem*>(raw);

    const int tid  = threadIdx.x;
    const int wid  = tid >> 5;
    const int lane = tid & 31;
    const float THR = __int_as_float(ANGLE_THR_BITS);

    // ---------------- init ----------------
    for (int j = tid; j < N; j += NT) {
        S.px[j]   = pts[3*j + 0];
        S.py[j]   = pts[3*j + 1];
        S.pz[j]   = pts[3*j + 2];
        S.slbl[j] = lbl[j];
    }
    if (tid < 10) {
        float l = anchors[tid*3+0], w = anchors[tid*3+1], h = anchors[tid*3+2];
        S.amdxy[tid] = fmaxf(l, w);
        S.amdz[tid]  = h;
        S.ar2[tid]   = __fdiv_rn(norm3_xla(l, w, h), 2.0f);
    }
    if (tid == 0) {
        S.sdl[0]  = 0;
        S.ccls[0] = lbl[0];
        // binary search for angle threshold: largest x with acos_xla(x) >= THR
        unsigned lo = ford(-1.0f), hi = ford(1.0f);
        while (hi - lo > 1u) {
            unsigned mid = lo + ((hi - lo) >> 1);
            if (acos_xla(ford_inv(mid)) >= THR) lo = mid; else hi = mid;
        }
        S.bval  = ford_inv(lo);
        S.ordb  = lo;
        S.flag0 = (acos_xla(0.0f) < THR) ? 1 : 0;
    }
    __syncthreads();

    const float    bval  = S.bval;
    const unsigned ordb  = S.ordb;
    const int      flag0 = S.flag0;

    // per-thread slot caches (slot k <-> point j = tid + k*512)
    int ml[PER];
#pragma unroll
    for (int k = 0; k < PER; ++k) ml[k] = S.slbl[tid + (k << 9)];
    unsigned mv   = (tid == 0) ? 1u : 0u;   // visited mask (point 0)
    unsigned memb = (tid == 0) ? 1u : 0u;   // current-cluster membership mask

    // shared scan state (identical in all threads)
    int cur = 0, cls = S.slbl[0];
    float cx = S.px[0], cy = S.py[0], cz = S.pz[0];
    float pn = norm3_xla(cx, cy, cz);

    // warp-0-only cluster accumulators (all 32 lanes redundant)
    int    lab = 0, cnt = 1;
    double sx = (double)cx, sy = (double)cy, sz = (double)cz;

    float dreg[PER];

    // ---------------- greedy scan: N-1 steps, 3 barriers each ----------------
    for (int step = 0; step < N - 1; ++step) {
        const float* __restrict__ drow = g_dmat + (size_t)cur * N;

        // ---- pass 1: coalesced dmat loads; class-split min + max; angle min --
        unsigned minA = 0xFFFFFFFFu, minB = 0xFFFFFFFFu, maxAll = 0u, xmb = 0xFFFFFFFFu;
#pragma unroll
        for (int k = 0; k < PER; ++k) {
            int j = tid + (k << 9);
            float d = __ldg(drow + j);
            dreg[k] = d;
            if (!(mv & (1u << k))) {
                unsigned db = __float_as_uint(d);     // d >= 0: bits are ordered
                if (ml[k] == cls) minA = min(minA, db);
                else              minB = min(minB, db);
                maxAll = max(maxAll, db);
            } else if (memb & (1u << k)) {
                float dx = __fsub_rn(S.px[j], cx);
                float dy = __fsub_rn(S.py[j], cy);
                float dz = __fsub_rn(S.pz[j], cz);
                float dt = -(__fadd_rn(__fadd_rn(__fmul_rn(cx,dx), __fmul_rn(cy,dy)),
                                       __fmul_rn(cz,dz)));
                float den = __fadd_rn(__fmul_rn(pn, d), 1e-8f);
                xmb = min(xmb, ford(__fdiv_rn(dt, den)));
            }
        }
        minA   = __reduce_min_sync(FULLMASK, minA);
        minB   = __reduce_min_sync(FULLMASK, minB);
        maxAll = __reduce_max_sync(FULLMASK, maxAll);
        xmb    = __reduce_min_sync(FULLMASK, xmb);
        if (lane == 0) {
            S.pminA[wid] = minA; S.pminB[wid] = minB;
            S.pmax[wid]  = maxAll; S.pxm[wid] = xmb;
        }
        __syncthreads();                                   // barrier 1

        // every warp re-reduces the 16 partials (this IS the broadcast)
        {
            unsigned a = (lane < NWP) ? S.pminA[lane] : 0xFFFFFFFFu;
            unsigned b = (lane < NWP) ? S.pminB[lane] : 0xFFFFFFFFu;
            unsigned c = (lane < NWP) ? S.pmax[lane]  : 0u;
            unsigned x = (lane < NWP) ? S.pxm[lane]   : 0xFFFFFFFFu;
            minA   = __reduce_min_sync(FULLMASK, a);
            minB   = __reduce_min_sync(FULLMASK, b);
            maxAll = __reduce_max_sync(FULLMASK, c);
            xmb    = __reduce_min_sync(FULLMASK, x);
        }

        const bool hasA = (minA != 0xFFFFFFFFu), hasB = (minB != 0xFFFFFFFFu);
        const float dmin = __uint_as_float(min(minA, minB));
        const float dmax = __uint_as_float(maxAll);
        const float Dn   = __fadd_rn(__fsub_rn(dmax, dmin), 1e-8f);
        const double Dnd = (double)Dn;

        // exact minimal costs per class + conservative x-space filters
        float costA = INF_F, costB = INF_F;
        if (hasA) {
            float xA = __fsub_rn(__uint_as_float(minA), dmin);
            costA = __fdiv_rn(xA, Dn);                 // + 0.0f exact
        }
        if (hasB) {
            float xB = __fsub_rn(__uint_as_float(minB), dmin);
            costB = __fadd_rn(__fdiv_rn(xB, Dn), 1.0f);
        }
        const float cstar = fminf(costA, costB);
        float thrA = NINF_F, thrB = NINF_F;
        if (hasA && costA == cstar) {
            double bq = (double)costA * (1.0 + 4.8e-7) + 1e-40;
            thrA = __double2float_ru(bq * Dnd);
        }
        if (hasB && costB == cstar) {
            double bq = ((double)costB - 1.0) + (double)costB * 2.4e-7 + 1e-40;
            bq = bq * (1.0 + 4.8e-7) + 1e-40;          // division-rounding slack
            thrB = __double2float_ru(bq * Dnd);
        }

        // angle verdict: warp 0 only (needed only in the tail)
        bool angflag = false;
        if (wid == 0) {
            float xc = fminf(fmaxf(ford_inv(xmb), -1.0f), 1.0f);
            if (xc == 0.0f) {
                angflag = (flag0 != 0);
            } else {
                long dlt = (long)ford(xc) - (long)ordb;
                if (dlt > -65536 && dlt < 65536) angflag = (acos_xla(xc) < THR);
                else                             angflag = (xc > bval);
            }
        }

        // ---- pass 2: exact-verified argmin (min index among cost == cstar) ----
        unsigned best = 0xFFFFFFFFu;
#pragma unroll
        for (int k = 0; k < PER; ++k) {
            if (!(mv & (1u << k))) {
                float x = __fsub_rn(dreg[k], dmin);
                bool isA = (ml[k] == cls);
                float thr = isA ? thrA : thrB;
                if (x <= thr) {
                    float q = __fdiv_rn(x, Dn);
                    float c = isA ? q : __fadd_rn(q, 1.0f);
                    if (c == cstar) best = min(best, (unsigned)(tid + (k << 9)));
                }
            }
        }
        best = __reduce_min_sync(FULLMASK, best);
        if (lane == 0) S.psel[wid] = best;
        __syncthreads();                                   // barrier 2
        {
            unsigned v = (lane < NWP) ? S.psel[lane] : 0xFFFFFFFFu;
            best = __reduce_min_sync(FULLMASK, v);
        }
        const int sel = (int)best;

        // ---- tail: warp-0 decision; broadcast newc bit ----
        if (wid == 0) {
            float cix = S.px[sel], ciy = S.py[sel], ciz = S.pz[sel];
            int   lci = S.slbl[sel];
            float ddx = __fsub_rn(cx, cix);
            float ddy = __fsub_rn(cy, ciy);
            float ddz = __fsub_rn(cz, ciz);
            float dn = norm3_xla(ddx, ddy, ddz);
            float cf = (float)cnt;
            float gx = __fdiv_rn((float)sx, cf);
            float gy = __fdiv_rn((float)sy, cf);
            float gz = __fdiv_rn((float)sz, cf);
            float en = norm3_xla(__fsub_rn(gx, cix), __fsub_rn(gy, ciy),
                                 __fsub_rn(gz, ciz));
            float a0 = S.amdxy[cls], a2 = S.amdz[cls], r2 = S.ar2[cls];
            bool newc = (fabsf(ddx) > a0) | (fabsf(ddy) > a0) | (fabsf(ddz) > a2) |
                        angflag | (lci != cls) | (dn > r2) | (en > r2);
            if (newc) {
                S.ccx[lab] = gx; S.ccy[lab] = gy; S.ccz[lab] = gz;  // same-value
                S.ccount[lab] = cnt;
                lab += 1;
                sx = (double)cix; sy = (double)ciy; sz = (double)ciz; cnt = 1;
                S.ccls[lab] = lci;
            } else {
                sx += (double)cix; sy += (double)ciy; sz += (double)ciz; cnt += 1;
            }
            S.sdl[sel] = lab;
            S.bnew = newc ? 1 : 0;
        }
        __syncthreads();                                   // barrier 3

        // ---- all threads: advance state ----
        int newcb = S.bnew;
        unsigned own = 0;
#pragma unroll
        for (int k = 0; k < PER; ++k)
            if (tid + (k << 9) == sel) own |= (1u << k);
        mv   |= own;
        memb  = (newcb ? 0u : memb) | own;
        cls = S.slbl[sel];
        cx = S.px[sel]; cy = S.py[sel]; cz = S.pz[sel];
        pn = norm3_xla(cx, cy, cz);
        cur = sel;
    }

    // flush final cluster (warp 0 holds the sums)
    if (wid == 0) {
        float cf = (float)cnt;
        S.ccx[lab] = __fdiv_rn((float)sx, cf);
        S.ccy[lab] = __fdiv_rn((float)sy, cf);
        S.ccz[lab] = __fdiv_rn((float)sz, cf);
        S.ccount[lab] = cnt;
        if (lane == 0) S.bnc = lab;   // num_clusters (exclusive)
    }
    __syncthreads();

    const int nc = S.bnc;

    // ---------------- stable descending sort by count (bitonic, 4096 keys) -----
    unsigned* skey = reinterpret_cast<unsigned*>(S.px);
    for (int i = tid; i < 4096; i += NT) {
        unsigned key = 0;
        if (i < nc) key = ((unsigned)S.ccount[i] << 12) | (4095u - (unsigned)i);
        skey[i] = key;
    }
    for (int i = tid; i < N; i += NT) { S.remap[i] = i; S.keep[i] = 1; }
    __syncthreads();

    for (int k = 2; k <= 4096; k <<= 1) {
        for (int j = k >> 1; j > 0; j >>= 1) {
#pragma unroll
            for (int e = 0; e < 8; ++e) {
                int i = tid + e * NT;
                int ixj = i ^ j;
                if (ixj > i) {
                    unsigned a2 = skey[i], b2 = skey[ixj];
                    bool descBlock = ((i & k) == 0);
                    if (descBlock ? (a2 < b2) : (a2 > b2)) { skey[i] = b2; skey[ixj] = a2; }
                }
            }
            __syncthreads();
        }
    }
    for (int i = tid; i < N; i += NT)
        if (i < nc) S.order[i] = 4095 - (int)(skey[i] & 4095u);
    __syncthreads();

    // ---------------- group order-positions by cluster class ----------
    if (wid < 10) {
        int c = wid, total = 0;
        int limit = (nc + 31) & ~31;
        for (int s = lane; s < limit; s += 32) {
            bool mm = (s < nc) && (S.ccls[S.order[s]] == c);
            unsigned bal = __ballot_sync(FULLMASK, mm);
            total += __popc(bal);
        }
        if (lane == 0) S.clsCount[c] = total;
    }
    __syncthreads();
    if (tid == 0) {
        int acc = 0;
        for (int c = 0; c < 10; ++c) { S.clsBase[c] = acc; acc += S.clsCount[c]; }
        S.clsBase[10] = acc;
    }
    __syncthreads();
    if (wid < 10) {
        int c = wid;
        int pos = S.clsBase[c];
        int limit = (nc + 31) & ~31;
        for (int s = lane; s < limit; s += 32) {
            bool mm = (s < nc) && (S.ccls[S.order[s]] == c);
            unsigned bal = __ballot_sync(FULLMASK, mm);
            if (mm) {
                int off = __popc(bal & ((1u << lane) - 1u));
                S.items[pos + off] = s;
            }
            pos += __popc(bal);
        }
    }
    __syncthreads();

    // ---------------- merge: independent per-class sequential chains ----------
    if (wid < 10) {
        int c    = wid;
        int base = S.clsBase[c];
        int len  = S.clsBase[c + 1] - base;
        float r2c = S.ar2[c];
        for (int t = 0; t < len; ++t) {
            __syncwarp();
            int ipos = S.items[base + t];
            if (!S.keep[ipos]) continue;
            int idx = S.order[ipos];
            float ax = S.ccx[idx], ay = S.ccy[idx], az = S.ccz[idx];
            for (int s = t + 1 + lane; s < len; s += 32) {
                int jpos = S.items[base + s];
                if (S.keep[jpos]) {
                    int jidx = S.order[jpos];
                    float dd = norm3_xla(__fsub_rn(S.ccx[jidx], ax),
                                         __fsub_rn(S.ccy[jidx], ay),
                                         __fsub_rn(S.ccz[jidx], az));
                    if (dd < r2c) {
                        S.keep[jpos]  = 0;
                        S.remap[jidx] = idx;
                    }
                }
            }
        }
    }
    __syncthreads();

    // ---------------- output (float32) ----------------
    for (int i = tid; i < N; i += NT)
        out[i] = (float)S.remap[S.sdl[i]];
}

extern "C" void kernel_launch(void* const* d_in, const int* in_sizes, int n_in,
                              void* d_out, int out_size)
{
    const float* pts     = nullptr;
    const int*   lbls    = nullptr;
    const float* anchors = nullptr;
    for (int i = 0; i < n_in; ++i) {
        if      (in_sizes[i] == N * 3) pts     = (const float*)d_in[i];
        else if (in_sizes[i] == N)     lbls    = (const int*)  d_in[i];
        else if (in_sizes[i] == 30)    anchors = (const float*)d_in[i];
    }
    if (!pts)     pts     = (const float*)d_in[0];
    if (!lbls)    lbls    = (const int*)  d_in[1];
    if (!anchors) anchors = (const float*)d_in[2];

    float* out = (float*)d_out;
    (void)out_size;

    static bool attr_done = false;
    if (!attr_done) {
        cudaFuncSetAttribute(frustum_cluster_kernel,
                             cudaFuncAttributeMaxDynamicSharedMemorySize,
                             (int)sizeof(Smem));
        attr_done = true;
    }
    dist_kernel<<<N, 256>>>(pts);
    frustum_cluster_kernel<<<1, NT, sizeof(Smem)>>>(pts, lbls, anchors, out);
}

// round 9
// speedup vs baseline: 3.1915x; 1.6682x over previous
#include <cuda_runtime.h>
#include <math.h>
#include <cstdint>

#define N    3072
#define NT   512
#define NWP  16
#define PER  6       // N / NT

#define ANGLE_THR_BITS 0x3FC90FDB   // f32(pi/2)
#define FULLMASK 0xffffffffu
#define INF_F  (__int_as_float(0x7f800000))

struct Smem {
    float px[N], py[N], pz[N];     // points (px reused as sort keys later)
    int   slbl[N];                 // per-point class
    int   sdl[N];                  // per-point cluster label
    float ccx[N], ccy[N], ccz[N];  // per-cluster centres
    int   ccount[N], ccls[N];      // per-cluster size / class
    int   order[N];                // scan: member list of current cluster; post: sort order
    int   items[N];                // post: class lists
    int   remap[N];                // post: merge remap
    unsigned char keep[N];
    unsigned pminA[NWP], pminB[NWP], pmax[NWP], psel[NWP];
    float amdxy[10], amdz[10], ar2[10];
    int   clsCount[10], clsBase[11];
    int   bnc, bnew;
    float bval; unsigned ordb; int flag0;   // angle threshold data
};

__device__ __forceinline__ float norm3_xla(float x, float y, float z) {
    float s = __fadd_rn(__fadd_rn(__fmul_rn(x, x), __fmul_rn(y, y)), __fmul_rn(z, z));
    return __fsqrt_rn(s);
}
// XLA acos lowering: 2*atan2(sqrt(1-x*x), 1+x); pi at x==-1. Same libdevice atan2f
// as the reference -> bit-identical.
__device__ __forceinline__ float acos_xla(float x) {
    float s = __fsqrt_rn(__fsub_rn(1.0f, __fmul_rn(x, x)));
    float r = 2.0f * atan2f(s, __fadd_rn(1.0f, x));
    if (x == -1.0f) r = __int_as_float(0x40490FDB);
    return r;
}
__device__ __forceinline__ unsigned ford(float f) {
    unsigned u = __float_as_uint(f);
    return (u & 0x80000000u) ? ~u : (u | 0x80000000u);
}
__device__ __forceinline__ float ford_inv(unsigned o) {
    unsigned u = (o & 0x80000000u) ? (o ^ 0x80000000u) : ~o;
    return __uint_as_float(u);
}

__global__ void __launch_bounds__(NT, 1)
frustum_cluster_kernel(const float* __restrict__ pts,
                       const int*   __restrict__ lbl,
                       const float* __restrict__ anchors,
                       float* __restrict__ out)
{
    extern __shared__ char raw[];
    Smem& S = *reinterpret_cast<Smem*>(raw);

    const int tid  = threadIdx.x;
    const int wid  = tid >> 5;
    const int lane = tid & 31;
    const float THR = __int_as_float(ANGLE_THR_BITS);

    // ---------------- init ----------------
    for (int j = tid; j < N; j += NT) {
        S.px[j]   = pts[3*j + 0];
        S.py[j]   = pts[3*j + 1];
        S.pz[j]   = pts[3*j + 2];
        S.slbl[j] = lbl[j];
    }
    if (tid < 10) {
        float l = anchors[tid*3+0], w = anchors[tid*3+1], h = anchors[tid*3+2];
        S.amdxy[tid] = fmaxf(l, w);
        S.amdz[tid]  = h;
        S.ar2[tid]   = __fdiv_rn(norm3_xla(l, w, h), 2.0f);
    }
    if (tid == 0) {
        S.sdl[0]   = 0;
        S.ccls[0]  = lbl[0];
        S.order[0] = 0;                      // member list = {0}
        // binary search: largest x with acos_xla(x) >= THR
        unsigned lo = ford(-1.0f), hi = ford(1.0f);
        while (hi - lo > 1u) {
            unsigned mid = lo + ((hi - lo) >> 1);
            if (acos_xla(ford_inv(mid)) >= THR) lo = mid; else hi = mid;
        }
        S.bval  = ford_inv(lo);
        S.ordb  = lo;
        S.flag0 = (acos_xla(0.0f) < THR) ? 1 : 0;
    }
    __syncthreads();

    const float    bval  = S.bval;
    const unsigned ordb  = S.ordb;
    const int      flag0 = S.flag0;

    // per-thread slot caches (slot k <-> point j = tid + k*512)
    float mx[PER], my_[PER], mz_[PER], sreg[PER];
    int   ml[PER];
#pragma unroll
    for (int k = 0; k < PER; ++k) {
        int j = tid + (k << 9);
        mx[k] = S.px[j]; my_[k] = S.py[j]; mz_[k] = S.pz[j];
        ml[k] = S.slbl[j];
    }
    unsigned mv = (tid == 0) ? 1u : 0u;      // visited mask (point 0)

    // shared scan state (identical in all threads)
    int cls = S.slbl[0];
    float cx = S.px[0], cy = S.py[0], cz = S.pz[0];

    // warp-0-only cluster state (lane-redundant)
    int    lab = 0, cnt = 1, mcnt = 1;
    float  pn = norm3_xla(cx, cy, cz);
    double sx = (double)cx, sy = (double)cy, sz = (double)cz;

    // ---------------- greedy scan: N-1 steps, 3 barriers each ----------------
    for (int step = 0; step < N - 1; ++step) {
        // ---- warp 0: angle pass over current member list ----
        bool angflag = false;
        if (wid == 0) {
            unsigned xmb = 0xFFFFFFFFu;
            for (int i = lane; i < mcnt; i += 32) {
                int j = S.order[i];
                float dx = __fsub_rn(S.px[j], cx);
                float dy = __fsub_rn(S.py[j], cy);
                float dz = __fsub_rn(S.pz[j], cz);
                float d  = norm3_xla(dx, dy, dz);
                float dt = -(__fadd_rn(__fadd_rn(__fmul_rn(cx,dx), __fmul_rn(cy,dy)),
                                       __fmul_rn(cz,dz)));
                float den = __fadd_rn(__fmul_rn(pn, d), 1e-8f);
                xmb = min(xmb, ford(__fdiv_rn(dt, den)));
            }
            xmb = __reduce_min_sync(FULLMASK, xmb);
            float xc = fminf(fmaxf(ford_inv(xmb), -1.0f), 1.0f);
            if (xc == 0.0f) {
                angflag = (flag0 != 0);
            } else {
                long dlt = (long)ford(xc) - (long)ordb;
                if (dlt > -65536 && dlt < 65536) angflag = (acos_xla(xc) < THR);
                else                             angflag = (xc > bval);
            }
        }

        // ---- pass 1: branch-free squared-dist reductions ----
        unsigned minA = 0xFFFFFFFFu, minB = 0xFFFFFFFFu, maxAll = 0u;
#pragma unroll
        for (int k = 0; k < PER; ++k) {
            float dx = __fsub_rn(mx[k],  cx);
            float dy = __fsub_rn(my_[k], cy);
            float dz = __fsub_rn(mz_[k], cz);
            float s  = __fadd_rn(__fadd_rn(__fmul_rn(dx,dx), __fmul_rn(dy,dy)),
                                 __fmul_rn(dz,dz));
            sreg[k] = s;
            unsigned sb = __float_as_uint(s);        // s >= 0: bits are ordered
            bool unv = ((mv >> k) & 1u) == 0u;
            bool isA = (ml[k] == cls);
            minA   = min(minA,   (unv &&  isA) ? sb : 0xFFFFFFFFu);
            minB   = min(minB,   (unv && !isA) ? sb : 0xFFFFFFFFu);
            maxAll = max(maxAll,  unv          ? sb : 0u);
        }
        minA   = __reduce_min_sync(FULLMASK, minA);
        minB   = __reduce_min_sync(FULLMASK, minB);
        maxAll = __reduce_max_sync(FULLMASK, maxAll);
        if (lane == 0) {
            S.pminA[wid] = minA; S.pminB[wid] = minB; S.pmax[wid] = maxAll;
        }
        __syncthreads();                                   // barrier 1

        // every warp re-reduces the partials (this IS the broadcast)
        {
            unsigned a = (lane < NWP) ? S.pminA[lane] : 0xFFFFFFFFu;
            unsigned b = (lane < NWP) ? S.pminB[lane] : 0xFFFFFFFFu;
            unsigned c = (lane < NWP) ? S.pmax[lane]  : 0u;
            minA   = __reduce_min_sync(FULLMASK, a);
            minB   = __reduce_min_sync(FULLMASK, b);
            maxAll = __reduce_max_sync(FULLMASK, c);
        }

        const bool hasA = (minA != 0xFFFFFFFFu), hasB = (minB != 0xFFFFFFFFu);
        const float dmin = __fsqrt_rn(__uint_as_float(min(minA, minB)));
        const float dmax = __fsqrt_rn(__uint_as_float(maxAll));
        const float Dn   = __fadd_rn(__fsub_rn(dmax, dmin), 1e-8f);

        // exact minimal costs per class (reference arithmetic on class-min d)
        float costA = INF_F, costB = INF_F;
        if (hasA) {
            float dA = __fsqrt_rn(__uint_as_float(minA));
            costA = __fdiv_rn(__fsub_rn(dA, dmin), Dn);          // + 0.0f exact
        }
        if (hasB) {
            float dB = __fsqrt_rn(__uint_as_float(minB));
            costB = __fadd_rn(__fdiv_rn(__fsub_rn(dB, dmin), Dn), 1.0f);
        }
        const float cstar = fminf(costA, costB);

        // conservative fp32 s-space admission thresholds (over-admit only)
        float thrSA = -1.0f, thrSB = -1.0f;
        if (hasA && costA == cstar) {
            float x = __fmul_ru(cstar, Dn);
            x = __fmul_ru(x, 1.000001f);
            x = __fadd_ru(x, 1e-37f);
            float dHi = __fmul_ru(__fadd_ru(dmin, x), 1.0000005f);
            thrSA = __fmul_ru(__fmul_ru(dHi, dHi), 1.0000005f);
        }
        if (hasB && costB == cstar) {
            float qHi = __fadd_ru(cstar, -1.0f);                 // exact (Sterbenz)
            qHi = __fadd_ru(qHi, __fadd_ru(__fmul_ru(cstar, 3e-7f), 1e-37f));
            float x = __fmul_ru(qHi, Dn);
            x = __fmul_ru(x, 1.000001f);
            x = __fadd_ru(x, 1e-37f);
            float dHi = __fmul_ru(__fadd_ru(dmin, x), 1.0000005f);
            thrSB = __fmul_ru(__fmul_ru(dHi, dHi), 1.0000005f);
        }

        // ---- pass 2: filtered exact verification, min index ----
        unsigned best = 0xFFFFFFFFu;
#pragma unroll
        for (int k = 0; k < PER; ++k) {
            bool unv = ((mv >> k) & 1u) == 0u;
            bool isA = (ml[k] == cls);
            float thr = isA ? thrSA : thrSB;
            if (unv && sreg[k] <= thr) {
                float d = __fsqrt_rn(sreg[k]);
                float q = __fdiv_rn(__fsub_rn(d, dmin), Dn);
                float c = isA ? q : __fadd_rn(q, 1.0f);
                if (c == cstar) best = min(best, (unsigned)(tid + (k << 9)));
            }
        }
        best = __reduce_min_sync(FULLMASK, best);
        if (lane == 0) S.psel[wid] = best;
        __syncthreads();                                   // barrier 2
        {
            unsigned v = (lane < NWP) ? S.psel[lane] : 0xFFFFFFFFu;
            best = __reduce_min_sync(FULLMASK, v);
        }
        const int sel = (int)best;

        // ---- warp-0 tail: decision + cluster state ----
        if (wid == 0) {
            float cix = S.px[sel], ciy = S.py[sel], ciz = S.pz[sel];
            int   lci = S.slbl[sel];
            float ddx = __fsub_rn(cx, cix);
            float ddy = __fsub_rn(cy, ciy);
            float ddz = __fsub_rn(cz, ciz);
            float dn = norm3_xla(ddx, ddy, ddz);
            float cf = (float)cnt;
            float gx = __fdiv_rn((float)sx, cf);
            float gy = __fdiv_rn((float)sy, cf);
            float gz = __fdiv_rn((float)sz, cf);
            float en = norm3_xla(__fsub_rn(gx, cix), __fsub_rn(gy, ciy),
                                 __fsub_rn(gz, ciz));
            float a0 = S.amdxy[cls], a2 = S.amdz[cls], r2 = S.ar2[cls];
            bool newc = (fabsf(ddx) > a0) | (fabsf(ddy) > a0) | (fabsf(ddz) > a2) |
                        angflag | (lci != cls) | (dn > r2) | (en > r2);
            if (newc) {
                if (lane == 0) {
                    S.ccx[lab] = gx; S.ccy[lab] = gy; S.ccz[lab] = gz;
                    S.ccount[lab] = cnt;
                    S.ccls[lab + 1] = lci;
                }
                lab += 1;
                sx = (double)cix; sy = (double)ciy; sz = (double)ciz; cnt = 1;
                mcnt = 0;
            } else {
                sx += (double)cix; sy += (double)ciy; sz += (double)ciz; cnt += 1;
            }
            if (lane == 0) {
                S.order[mcnt] = sel;
                S.sdl[sel] = lab;
                S.bnew = newc ? 1 : 0;
            }
            mcnt += 1;
            pn = norm3_xla(cix, ciy, ciz);
        }
        __syncthreads();                                   // barrier 3

        // ---- all threads: advance shared state ----
#pragma unroll
        for (int k = 0; k < PER; ++k)
            mv |= ((unsigned)(tid + (k << 9) == sel)) << k;
        cls = S.slbl[sel];
        cx = S.px[sel]; cy = S.py[sel]; cz = S.pz[sel];
    }

    // flush final cluster (warp 0 holds the sums)
    if (wid == 0 && lane == 0) {
        float cf = (float)cnt;
        S.ccx[lab] = __fdiv_rn((float)sx, cf);
        S.ccy[lab] = __fdiv_rn((float)sy, cf);
        S.ccz[lab] = __fdiv_rn((float)sz, cf);
        S.ccount[lab] = cnt;
        S.bnc = lab;   // num_clusters (exclusive)
    }
    __syncthreads();

    const int nc = S.bnc;

    // ---------------- stable descending sort by count (bitonic, 4096 keys) -----
    unsigned* skey = reinterpret_cast<unsigned*>(S.px);
    for (int i = tid; i < 4096; i += NT) {
        unsigned key = 0;
        if (i < nc) key = ((unsigned)S.ccount[i] << 12) | (4095u - (unsigned)i);
        skey[i] = key;
    }
    for (int i = tid; i < N; i += NT) { S.remap[i] = i; S.keep[i] = 1; }
    __syncthreads();

    for (int k = 2; k <= 4096; k <<= 1) {
        for (int j = k >> 1; j > 0; j >>= 1) {
#pragma unroll
            for (int e = 0; e < 8; ++e) {
                int i = tid + e * NT;
                int ixj = i ^ j;
                if (ixj > i) {
                    unsigned a2 = skey[i], b2 = skey[ixj];
                    bool descBlock = ((i & k) == 0);
                    if (descBlock ? (a2 < b2) : (a2 > b2)) { skey[i] = b2; skey[ixj] = a2; }
                }
            }
            __syncthreads();
        }
    }
    for (int i = tid; i < N; i += NT)
        if (i < nc) S.order[i] = 4095 - (int)(skey[i] & 4095u);
    __syncthreads();

    // ---------------- group order-positions by cluster class ----------
    if (wid < 10) {
        int c = wid, total = 0;
        int limit = (nc + 31) & ~31;
        for (int s = lane; s < limit; s += 32) {
            bool mm = (s < nc) && (S.ccls[S.order[s]] == c);
            unsigned bal = __ballot_sync(FULLMASK, mm);
            total += __popc(bal);
        }
        if (lane == 0) S.clsCount[c] = total;
    }
    __syncthreads();
    if (tid == 0) {
        int acc = 0;
        for (int c = 0; c < 10; ++c) { S.clsBase[c] = acc; acc += S.clsCount[c]; }
        S.clsBase[10] = acc;
    }
    __syncthreads();
    if (wid < 10) {
        int c = wid;
        int pos = S.clsBase[c];
        int limit = (nc + 31) & ~31;
        for (int s = lane; s < limit; s += 32) {
            bool mm = (s < nc) && (S.ccls[S.order[s]] == c);
            unsigned bal = __ballot_sync(FULLMASK, mm);
            if (mm) {
                int off = __popc(bal & ((1u << lane) - 1u));
                S.items[pos + off] = s;
            }
            pos += __popc(bal);
        }
    }
    __syncthreads();

    // ---------------- merge: independent per-class sequential chains ----------
    if (wid < 10) {
        int c    = wid;
        int base = S.clsBase[c];
        int len  = S.clsBase[c + 1] - base;
        float r2c = S.ar2[c];
        for (int t = 0; t < len; ++t) {
            __syncwarp();
            int ipos = S.items[base + t];
            if (!S.keep[ipos]) continue;
            int idx = S.order[ipos];
            float ax = S.ccx[idx], ay = S.ccy[idx], az = S.ccz[idx];
            for (int s = t + 1 + lane; s < len; s += 32) {
                int jpos = S.items[base + s];
                if (S.keep[jpos]) {
                    int jidx = S.order[jpos];
                    float dd = norm3_xla(__fsub_rn(S.ccx[jidx], ax),
                                         __fsub_rn(S.ccy[jidx], ay),
                                         __fsub_rn(S.ccz[jidx], az));
                    if (dd < r2c) {
                        S.keep[jpos]  = 0;
                        S.remap[jidx] = idx;
                    }
                }
            }
        }
    }
    __syncthreads();

    // ---------------- output (float32) ----------------
    for (int i = tid; i < N; i += NT)
        out[i] = (float)S.remap[S.sdl[i]];
}

extern "C" void kernel_launch(void* const* d_in, const int* in_sizes, int n_in,
                              void* d_out, int out_size)
{
    const float* pts     = nullptr;
    const int*   lbls    = nullptr;
    const float* anchors = nullptr;
    for (int i = 0; i < n_in; ++i) {
        if      (in_sizes[i] == N * 3) pts     = (const float*)d_in[i];
        else if (in_sizes[i] == N)     lbls    = (const int*)  d_in[i];
        else if (in_sizes[i] == 30)    anchors = (const float*)d_in[i];
    }
    if (!pts)     pts     = (const float*)d_in[0];
    if (!lbls)    lbls    = (const int*)  d_in[1];
    if (!anchors) anchors = (const float*)d_in[2];

    float* out = (float*)d_out;
    (void)out_size;

    static bool attr_done = false;
    if (!attr_done) {
        cudaFuncSetAttribute(frustum_cluster_kernel,
                             cudaFuncAttributeMaxDynamicSharedMemorySize,
                             (int)sizeof(Smem));
        attr_done = true;
    }
    frustum_cluster_kernel<<<1, NT, sizeof(Smem)>>>(pts, lbls, anchors, out);
}

// round 10
// speedup vs baseline: 4.5415x; 1.4230x over previous
#include <cuda_runtime.h>
#include <math.h>
#include <cstdint>

#define N    3072
#define NT   512
#define NWP  16
#define WT   480     // worker threads (warps 1..15)
#define PER  7       // ceil(N / WT)

#define ANGLE_THR_BITS 0x3FC90FDB   // f32(pi/2)
#define FULLMASK 0xffffffffu
#define INF_F  (__int_as_float(0x7f800000))

struct Smem {
    float px[N], py[N], pz[N];     // points (px reused as sort keys later)
    int   slbl[N];                 // per-point class
    int   sdl[N];                  // per-point cluster label
    float ccx[N], ccy[N], ccz[N];  // per-cluster centres
    int   ccount[N], ccls[N];      // per-cluster size / class
    int   order[N];                // scan: member list of current cluster; post: sort order
    int   items[N];                // post: class lists
    int   remap[N];                // post: merge remap
    unsigned char keep[N];
    unsigned pminA[NWP], pminB[NWP], pmax[NWP], psel[NWP];
    float amdxy[10], amdz[10], ar2[10];
    int   clsCount[10], clsBase[11];
    int   bnc;
    float bval; unsigned ordb; int flag0;   // angle threshold data
};

__device__ __forceinline__ float norm3_xla(float x, float y, float z) {
    float s = __fadd_rn(__fadd_rn(__fmul_rn(x, x), __fmul_rn(y, y)), __fmul_rn(z, z));
    return __fsqrt_rn(s);
}
// XLA acos lowering: 2*atan2(sqrt(1-x*x), 1+x); pi at x==-1. Same libdevice atan2f
// as the reference -> bit-identical.
__device__ __forceinline__ float acos_xla(float x) {
    float s = __fsqrt_rn(__fsub_rn(1.0f, __fmul_rn(x, x)));
    float r = 2.0f * atan2f(s, __fadd_rn(1.0f, x));
    if (x == -1.0f) r = __int_as_float(0x40490FDB);
    return r;
}
__device__ __forceinline__ unsigned ford(float f) {
    unsigned u = __float_as_uint(f);
    return (u & 0x80000000u) ? ~u : (u | 0x80000000u);
}
__device__ __forceinline__ float ford_inv(unsigned o) {
    unsigned u = (o & 0x80000000u) ? (o ^ 0x80000000u) : ~o;
    return __uint_as_float(u);
}

__global__ void __launch_bounds__(NT, 1)
frustum_cluster_kernel(const float* __restrict__ pts,
                       const int*   __restrict__ lbl,
                       const float* __restrict__ anchors,
                       float* __restrict__ out)
{
    extern __shared__ char raw[];
    Smem& S = *reinterpret_cast<Smem*>(raw);

    const int tid  = threadIdx.x;
    const int wid  = tid >> 5;
    const int lane = tid & 31;
    const float THR = __int_as_float(ANGLE_THR_BITS);

    // ---------------- init ----------------
    for (int j = tid; j < N; j += NT) {
        S.px[j]   = pts[3*j + 0];
        S.py[j]   = pts[3*j + 1];
        S.pz[j]   = pts[3*j + 2];
        S.slbl[j] = lbl[j];
    }
    if (tid < 10) {
        float l = anchors[tid*3+0], w = anchors[tid*3+1], h = anchors[tid*3+2];
        S.amdxy[tid] = fmaxf(l, w);
        S.amdz[tid]  = h;
        S.ar2[tid]   = __fdiv_rn(norm3_xla(l, w, h), 2.0f);
    }
    if (tid == 0) {
        S.sdl[0]   = 0;
        S.ccls[0]  = lbl[0];
        S.order[0] = 0;                      // member list = {0}
        // binary search: largest x with acos_xla(x) >= THR
        unsigned lo = ford(-1.0f), hi = ford(1.0f);
        while (hi - lo > 1u) {
            unsigned mid = lo + ((hi - lo) >> 1);
            if (acos_xla(ford_inv(mid)) >= THR) lo = mid; else hi = mid;
        }
        S.bval  = ford_inv(lo);
        S.ordb  = lo;
        S.flag0 = (acos_xla(0.0f) < THR) ? 1 : 0;
    }
    __syncthreads();

    const float    bval  = S.bval;
    const unsigned ordb  = S.ordb;
    const int      flag0 = S.flag0;

    // worker slot caches (slot k <-> point j = (tid-32) + k*480)
    float mx[PER], my_[PER], mz_[PER], sreg[PER];
    int   ml[PER];
    unsigned mv = 0;                        // visited/invalid mask
    if (wid >= 1) {
        int wtid = tid - 32;
#pragma unroll
        for (int k = 0; k < PER; ++k) {
            int j = wtid + k * WT;
            bool v = (j < N);
            mx[k]  = v ? S.px[j] : 0.0f;
            my_[k] = v ? S.py[j] : 0.0f;
            mz_[k] = v ? S.pz[j] : 0.0f;
            ml[k]  = v ? S.slbl[j] : -1;
            if (!v)     mv |= (1u << k);    // invalid -> permanently "visited"
            if (j == 0) mv |= (1u << k);    // point 0 starts visited
        }
    }

    // shared scan state (all threads)
    int cls = S.slbl[0];
    float cx = S.px[0], cy = S.py[0], cz = S.pz[0];

    // warp-0-only cluster state (lane-redundant)
    int    lab = 0, cnt = 1, mcnt = 1;
    float  pn = norm3_xla(cx, cy, cz);
    double sx = (double)cx, sy = (double)cy, sz = (double)cz;

    // ---------------- greedy scan: N-1 steps, ONE full barrier each ----------
    for (int step = 0; step < N - 1; ++step) {
        bool angflag = false;

        if (wid == 0) {
            // ---- serial engine: angle pass over current member list ----
            unsigned xmb = 0xFFFFFFFFu;
            for (int i = lane; i < mcnt; i += 32) {
                int j = S.order[i];
                float dx = __fsub_rn(S.px[j], cx);
                float dy = __fsub_rn(S.py[j], cy);
                float dz = __fsub_rn(S.pz[j], cz);
                float d  = norm3_xla(dx, dy, dz);
                float dt = -(__fadd_rn(__fadd_rn(__fmul_rn(cx,dx), __fmul_rn(cy,dy)),
                                       __fmul_rn(cz,dz)));
                float den = __fadd_rn(__fmul_rn(pn, d), 1e-8f);
                xmb = min(xmb, ford(__fdiv_rn(dt, den)));
            }
            xmb = __reduce_min_sync(FULLMASK, xmb);
            float xc = fminf(fmaxf(ford_inv(xmb), -1.0f), 1.0f);
            if (xc == 0.0f) {
                angflag = (flag0 != 0);
            } else {
                long dlt = (long)ford(xc) - (long)ordb;
                if (dlt > -65536 && dlt < 65536) angflag = (acos_xla(xc) < THR);
                else                             angflag = (xc > bval);
            }
        } else {
            // ---- candidate engine: pass 1 (branch-free squared-dist) ----
            unsigned minA = 0xFFFFFFFFu, minB = 0xFFFFFFFFu, maxAll = 0u;
#pragma unroll
            for (int k = 0; k < PER; ++k) {
                float dx = __fsub_rn(mx[k],  cx);
                float dy = __fsub_rn(my_[k], cy);
                float dz = __fsub_rn(mz_[k], cz);
                float s  = __fadd_rn(__fadd_rn(__fmul_rn(dx,dx), __fmul_rn(dy,dy)),
                                     __fmul_rn(dz,dz));
                sreg[k] = s;
                unsigned sb = __float_as_uint(s);    // s >= 0: bits ordered
                bool unv = ((mv >> k) & 1u) == 0u;
                bool isA = (ml[k] == cls);
                minA   = min(minA,   (unv &&  isA) ? sb : 0xFFFFFFFFu);
                minB   = min(minB,   (unv && !isA) ? sb : 0xFFFFFFFFu);
                maxAll = max(maxAll,  unv          ? sb : 0u);
            }
            minA   = __reduce_min_sync(FULLMASK, minA);
            minB   = __reduce_min_sync(FULLMASK, minB);
            maxAll = __reduce_max_sync(FULLMASK, maxAll);
            if (lane == 0) {
                S.pminA[wid] = minA; S.pminB[wid] = minB; S.pmax[wid] = maxAll;
            }
            // workers-only barrier (publishes partials among the 480)
            asm volatile("bar.sync 1, %0;" :: "r"(WT) : "memory");

            // re-reduce the 15 worker partials (lanes 1..15)
            {
                bool ok = (lane >= 1 && lane < NWP);
                unsigned a = ok ? S.pminA[lane] : 0xFFFFFFFFu;
                unsigned b = ok ? S.pminB[lane] : 0xFFFFFFFFu;
                unsigned c = ok ? S.pmax[lane]  : 0u;
                minA   = __reduce_min_sync(FULLMASK, a);
                minB   = __reduce_min_sync(FULLMASK, b);
                maxAll = __reduce_max_sync(FULLMASK, c);
            }

            const bool hasA = (minA != 0xFFFFFFFFu), hasB = (minB != 0xFFFFFFFFu);
            const float dmin = __fsqrt_rn(__uint_as_float(min(minA, minB)));
            const float dmax = __fsqrt_rn(__uint_as_float(maxAll));
            const float Dn   = __fadd_rn(__fsub_rn(dmax, dmin), 1e-8f);

            // exact minimal costs per class (reference arithmetic on class-min d)
            float costA = INF_F, costB = INF_F;
            if (hasA) {
                float dA = __fsqrt_rn(__uint_as_float(minA));
                costA = __fdiv_rn(__fsub_rn(dA, dmin), Dn);        // + 0.0f exact
            }
            if (hasB) {
                float dB = __fsqrt_rn(__uint_as_float(minB));
                costB = __fadd_rn(__fdiv_rn(__fsub_rn(dB, dmin), Dn), 1.0f);
            }
            const float cstar = fminf(costA, costB);

            // conservative fp32 s-space admission thresholds (over-admit only)
            float thrSA = -1.0f, thrSB = -1.0f;
            if (hasA && costA == cstar) {
                float x = __fmul_ru(cstar, Dn);
                x = __fmul_ru(x, 1.000001f);
                x = __fadd_ru(x, 1e-37f);
                float dHi = __fmul_ru(__fadd_ru(dmin, x), 1.0000005f);
                thrSA = __fmul_ru(__fmul_ru(dHi, dHi), 1.0000005f);
            }
            if (hasB && costB == cstar) {
                float qHi = __fadd_ru(cstar, -1.0f);               // exact (Sterbenz)
                qHi = __fadd_ru(qHi, __fadd_ru(__fmul_ru(cstar, 3e-7f), 1e-37f));
                float x = __fmul_ru(qHi, Dn);
                x = __fmul_ru(x, 1.000001f);
                x = __fadd_ru(x, 1e-37f);
                float dHi = __fmul_ru(__fadd_ru(dmin, x), 1.0000005f);
                thrSB = __fmul_ru(__fmul_ru(dHi, dHi), 1.0000005f);
            }

            // ---- pass 2: filtered exact verification, min index ----
            unsigned best = 0xFFFFFFFFu;
            int wtid = tid - 32;
#pragma unroll
            for (int k = 0; k < PER; ++k) {
                bool unv = ((mv >> k) & 1u) == 0u;
                bool isA = (ml[k] == cls);
                float thr = isA ? thrSA : thrSB;
                if (unv && sreg[k] <= thr) {
                    float d = __fsqrt_rn(sreg[k]);
                    float q = __fdiv_rn(__fsub_rn(d, dmin), Dn);
                    float c = isA ? q : __fadd_rn(q, 1.0f);
                    if (c == cstar) best = min(best, (unsigned)(wtid + k * WT));
                }
            }
            best = __reduce_min_sync(FULLMASK, best);
            if (lane == 0) S.psel[wid] = best;
        }

        __syncthreads();                     // the ONE full barrier: publishes psel

        // all threads: reduce the 15 worker psel entries -> sel
        int sel;
        {
            bool ok = (lane >= 1 && lane < NWP);
            unsigned v = ok ? S.psel[lane] : 0xFFFFFFFFu;
            sel = (int)__reduce_min_sync(FULLMASK, v);
        }

        if (wid == 0) {
            // ---- serial engine: tail decision + cluster state ----
            float cix = S.px[sel], ciy = S.py[sel], ciz = S.pz[sel];
            int   lci = S.slbl[sel];
            float ddx = __fsub_rn(cx, cix);
            float ddy = __fsub_rn(cy, ciy);
            float ddz = __fsub_rn(cz, ciz);
            float dn = norm3_xla(ddx, ddy, ddz);
            float cf = (float)cnt;
            float gx = __fdiv_rn((float)sx, cf);
            float gy = __fdiv_rn((float)sy, cf);
            float gz = __fdiv_rn((float)sz, cf);
            float en = norm3_xla(__fsub_rn(gx, cix), __fsub_rn(gy, ciy),
                                 __fsub_rn(gz, ciz));
            float a0 = S.amdxy[cls], a2 = S.amdz[cls], r2 = S.ar2[cls];
            bool newc = (fabsf(ddx) > a0) | (fabsf(ddy) > a0) | (fabsf(ddz) > a2) |
                        angflag | (lci != cls) | (dn > r2) | (en > r2);
            if (newc) {
                if (lane == 0) {
                    S.ccx[lab] = gx; S.ccy[lab] = gy; S.ccz[lab] = gz;
                    S.ccount[lab] = cnt;
                    S.ccls[lab + 1] = lci;
                }
                lab += 1;
                sx = (double)cix; sy = (double)ciy; sz = (double)ciz; cnt = 1;
                mcnt = 0;
            } else {
                sx += (double)cix; sy += (double)ciy; sz += (double)ciz; cnt += 1;
            }
            if (lane == 0) {
                S.order[mcnt] = sel;
                S.sdl[sel] = lab;
            }
            mcnt += 1;
            pn = norm3_xla(cix, ciy, ciz);
            __syncwarp();                    // order[] write -> next angle pass reads
        } else {
            // workers: mark sel visited if owned
            int wtid = tid - 32;
#pragma unroll
            for (int k = 0; k < PER; ++k)
                mv |= ((unsigned)(wtid + k * WT == sel)) << k;
        }

        // all threads: advance shared state (constants, no race)
        cls = S.slbl[sel];
        cx = S.px[sel]; cy = S.py[sel]; cz = S.pz[sel];
    }

    // flush final cluster (warp 0 holds the sums)
    if (wid == 0 && lane == 0) {
        float cf = (float)cnt;
        S.ccx[lab] = __fdiv_rn((float)sx, cf);
        S.ccy[lab] = __fdiv_rn((float)sy, cf);
        S.ccz[lab] = __fdiv_rn((float)sz, cf);
        S.ccount[lab] = cnt;
        S.bnc = lab;   // num_clusters (exclusive)
    }
    __syncthreads();

    const int nc = S.bnc;

    // ---------------- stable descending sort by count (bitonic, 4096 keys) -----
    unsigned* skey = reinterpret_cast<unsigned*>(S.px);
    for (int i = tid; i < 4096; i += NT) {
        unsigned key = 0;
        if (i < nc) key = ((unsigned)S.ccount[i] << 12) | (4095u - (unsigned)i);
        skey[i] = key;
    }
    for (int i = tid; i < N; i += NT) { S.remap[i] = i; S.keep[i] = 1; }
    __syncthreads();

    for (int k = 2; k <= 4096; k <<= 1) {
        for (int j = k >> 1; j > 0; j >>= 1) {
#pragma unroll
            for (int e = 0; e < 8; ++e) {
                int i = tid + e * NT;
                int ixj = i ^ j;
                if (ixj > i) {
                    unsigned a2 = skey[i], b2 = skey[ixj];
                    bool descBlock = ((i & k) == 0);
                    if (descBlock ? (a2 < b2) : (a2 > b2)) { skey[i] = b2; skey[ixj] = a2; }
                }
            }
            __syncthreads();
        }
    }
    for (int i = tid; i < N; i += NT)
        if (i < nc) S.order[i] = 4095 - (int)(skey[i] & 4095u);
    __syncthreads();

    // ---------------- group order-positions by cluster class ----------
    if (wid < 10) {
        int c = wid, total = 0;
        int limit = (nc + 31) & ~31;
        for (int s = lane; s < limit; s += 32) {
            bool mm = (s < nc) && (S.ccls[S.order[s]] == c);
            unsigned bal = __ballot_sync(FULLMASK, mm);
            total += __popc(bal);
        }
        if (lane == 0) S.clsCount[c] = total;
    }
    __syncthreads();
    if (tid == 0) {
        int acc = 0;
        for (int c = 0; c < 10; ++c) { S.clsBase[c] = acc; acc += S.clsCount[c]; }
        S.clsBase[10] = acc;
    }
    __syncthreads();
    if (wid < 10) {
        int c = wid;
        int pos = S.clsBase[c];
        int limit = (nc + 31) & ~31;
        for (int s = lane; s < limit; s += 32) {
            bool mm = (s < nc) && (S.ccls[S.order[s]] == c);
            unsigned bal = __ballot_sync(FULLMASK, mm);
            if (mm) {
                int off = __popc(bal & ((1u << lane) - 1u));
                S.items[pos + off] = s;
            }
            pos += __popc(bal);
        }
    }
    __syncthreads();

    // ---------------- merge: independent per-class sequential chains ----------
    if (wid < 10) {
        int c    = wid;
        int base = S.clsBase[c];
        int len  = S.clsBase[c + 1] - base;
        float r2c = S.ar2[c];
        for (int t = 0; t < len; ++t) {
            __syncwarp();
            int ipos = S.items[base + t];
            if (!S.keep[ipos]) continue;
            int idx = S.order[ipos];
            float ax = S.ccx[idx], ay = S.ccy[idx], az = S.ccz[idx];
            for (int s = t + 1 + lane; s < len; s += 32) {
                int jpos = S.items[base + s];
                if (S.keep[jpos]) {
                    int jidx = S.order[jpos];
                    float dd = norm3_xla(__fsub_rn(S.ccx[jidx], ax),
                                         __fsub_rn(S.ccy[jidx], ay),
                                         __fsub_rn(S.ccz[jidx], az));
                    if (dd < r2c) {
                        S.keep[jpos]  = 0;
                        S.remap[jidx] = idx;
                    }
                }
            }
        }
    }
    __syncthreads();

    // ---------------- output (float32) ----------------
    for (int i = tid; i < N; i += NT)
        out[i] = (float)S.remap[S.sdl[i]];
}

extern "C" void kernel_launch(void* const* d_in, const int* in_sizes, int n_in,
                              void* d_out, int out_size)
{
    const float* pts     = nullptr;
    const int*   lbls    = nullptr;
    const float* anchors = nullptr;
    for (int i = 0; i < n_in; ++i) {
        if      (in_sizes[i] == N * 3) pts     = (const float*)d_in[i];
        else if (in_sizes[i] == N)     lbls    = (const int*)  d_in[i];
        else if (in_sizes[i] == 30)    anchors = (const float*)d_in[i];
    }
    if (!pts)     pts     = (const float*)d_in[0];
    if (!lbls)    lbls    = (const int*)  d_in[1];
    if (!anchors) anchors = (const float*)d_in[2];

    float* out = (float*)d_out;
    (void)out_size;

    static bool attr_done = false;
    if (!attr_done) {
        cudaFuncSetAttribute(frustum_cluster_kernel,
                             cudaFuncAttributeMaxDynamicSharedMemorySize,
                             (int)sizeof(Smem));
        attr_done = true;
    }
    frustum_cluster_kernel<<<1, NT, sizeof(Smem)>>>(pts, lbls, anchors, out);
}

// round 11
// speedup vs baseline: 5.0363x; 1.1089x over previous
#include <cuda_runtime.h>
#include <math.h>
#include <cstdint>

#define N    3072
#define NT   512
#define NWP  16
#define WT   480     // worker threads (warps 1..15)
#define PER  7       // ceil(N / WT)

#define ANGLE_THR_BITS 0x3FC90FDB   // f32(pi/2)
#define FULLMASK 0xffffffffu
#define INF_F  (__int_as_float(0x7f800000))

struct Smem {
    float px[N], py[N], pz[N];     // points (px reused as sort keys later)
    int   slbl[N];                 // per-point class
    int   sdl[N];                  // per-point cluster label
    float ccx[N], ccy[N], ccz[N];  // per-cluster centres
    int   ccount[N], ccls[N];      // per-cluster size / class
    int   order[N];                // scan: member list of current cluster; post: sort order
    int   items[N];                // post: class lists
    int   remap[N];                // post: merge remap
    int   selq[N];                 // sel sequence queue (workers -> warp 0)
    unsigned char keep[N];
    unsigned pminA[NWP], pminB[NWP], pmax[NWP], psel[NWP];
    float amdxy[10], amdz[10], ar2[10];
    int   clsCount[10], clsBase[11];
    int   bnc;
    float bval; unsigned ordb; int flag0;   // angle threshold data
};

__device__ __forceinline__ float norm3_xla(float x, float y, float z) {
    float s = __fadd_rn(__fadd_rn(__fmul_rn(x, x), __fmul_rn(y, y)), __fmul_rn(z, z));
    return __fsqrt_rn(s);
}
// XLA acos lowering: 2*atan2(sqrt(1-x*x), 1+x); pi at x==-1. Same libdevice atan2f
// as the reference -> bit-identical.
__device__ __forceinline__ float acos_xla(float x) {
    float s = __fsqrt_rn(__fsub_rn(1.0f, __fmul_rn(x, x)));
    float r = 2.0f * atan2f(s, __fadd_rn(1.0f, x));
    if (x == -1.0f) r = __int_as_float(0x40490FDB);
    return r;
}
__device__ __forceinline__ unsigned ford(float f) {
    unsigned u = __float_as_uint(f);
    return (u & 0x80000000u) ? ~u : (u | 0x80000000u);
}
__device__ __forceinline__ float ford_inv(unsigned o) {
    unsigned u = (o & 0x80000000u) ? (o ^ 0x80000000u) : ~o;
    return __uint_as_float(u);
}

__global__ void __launch_bounds__(NT, 1)
frustum_cluster_kernel(const float* __restrict__ pts,
                       const int*   __restrict__ lbl,
                       const float* __restrict__ anchors,
                       float* __restrict__ out)
{
    extern __shared__ char raw[];
    Smem& S = *reinterpret_cast<Smem*>(raw);

    const int tid  = threadIdx.x;
    const int wid  = tid >> 5;
    const int lane = tid & 31;
    const float THR = __int_as_float(ANGLE_THR_BITS);

    // ---------------- init ----------------
    for (int j = tid; j < N; j += NT) {
        S.px[j]   = pts[3*j + 0];
        S.py[j]   = pts[3*j + 1];
        S.pz[j]   = pts[3*j + 2];
        S.slbl[j] = lbl[j];
        S.selq[j] = -1;
    }
    if (tid < 10) {
        float l = anchors[tid*3+0], w = anchors[tid*3+1], h = anchors[tid*3+2];
        S.amdxy[tid] = fmaxf(l, w);
        S.amdz[tid]  = h;
        S.ar2[tid]   = __fdiv_rn(norm3_xla(l, w, h), 2.0f);
    }
    if (tid == 0) {
        S.sdl[0]   = 0;
        S.ccls[0]  = lbl[0];
        S.order[0] = 0;                      // member list = {0}
        // binary search: largest x with acos_xla(x) >= THR
        unsigned lo = ford(-1.0f), hi = ford(1.0f);
        while (hi - lo > 1u) {
            unsigned mid = lo + ((hi - lo) >> 1);
            if (acos_xla(ford_inv(mid)) >= THR) lo = mid; else hi = mid;
        }
        S.bval  = ford_inv(lo);
        S.ordb  = lo;
        S.flag0 = (acos_xla(0.0f) < THR) ? 1 : 0;
    }
    __syncthreads();

    if (wid == 0) {
        // ================= serial engine (warp 0): trails the workers =========
        const float    bval  = S.bval;
        const unsigned ordb  = S.ordb;
        const int      flag0 = S.flag0;
        volatile int*  vq    = S.selq;

        int   cls = S.slbl[0];
        float cx = S.px[0], cy = S.py[0], cz = S.pz[0];
        float pn = norm3_xla(cx, cy, cz);
        int    lab = 0, cnt = 1, mcnt = 1;
        double sx = (double)cx, sy = (double)cy, sz = (double)cz;

        for (int step = 0; step < N - 1; ++step) {
            // ---- angle pass over current member list (independent of sel) ----
            unsigned xmb = 0xFFFFFFFFu;
            for (int i = lane; i < mcnt; i += 32) {
                int j = S.order[i];
                float dx = __fsub_rn(S.px[j], cx);
                float dy = __fsub_rn(S.py[j], cy);
                float dz = __fsub_rn(S.pz[j], cz);
                float d  = norm3_xla(dx, dy, dz);
                float dt = -(__fadd_rn(__fadd_rn(__fmul_rn(cx,dx), __fmul_rn(cy,dy)),
                                       __fmul_rn(cz,dz)));
                float den = __fadd_rn(__fmul_rn(pn, d), 1e-8f);
                xmb = min(xmb, ford(__fdiv_rn(dt, den)));
            }
            xmb = __reduce_min_sync(FULLMASK, xmb);
            float xc = fminf(fmaxf(ford_inv(xmb), -1.0f), 1.0f);
            bool angflag;
            if (xc == 0.0f) {
                angflag = (flag0 != 0);
            } else {
                long dlt = (long)ford(xc) - (long)ordb;
                if (dlt > -65536 && dlt < 65536) angflag = (acos_xla(xc) < THR);
                else                             angflag = (xc > bval);
            }

            // ---- consume sel from the queue (workers run ahead) ----
            int sel;
            do { sel = vq[step]; } while (sel < 0);

            // ---- tail decision + cluster state ----
            float cix = S.px[sel], ciy = S.py[sel], ciz = S.pz[sel];
            int   lci = S.slbl[sel];
            float ddx = __fsub_rn(cx, cix);
            float ddy = __fsub_rn(cy, ciy);
            float ddz = __fsub_rn(cz, ciz);
            float dn = norm3_xla(ddx, ddy, ddz);
            float cf = (float)cnt;
            float gx = __fdiv_rn((float)sx, cf);
            float gy = __fdiv_rn((float)sy, cf);
            float gz = __fdiv_rn((float)sz, cf);
            float en = norm3_xla(__fsub_rn(gx, cix), __fsub_rn(gy, ciy),
                                 __fsub_rn(gz, ciz));
            float a0 = S.amdxy[cls], a2 = S.amdz[cls], r2 = S.ar2[cls];
            bool newc = (fabsf(ddx) > a0) | (fabsf(ddy) > a0) | (fabsf(ddz) > a2) |
                        angflag | (lci != cls) | (dn > r2) | (en > r2);
            if (newc) {
                if (lane == 0) {
                    S.ccx[lab] = gx; S.ccy[lab] = gy; S.ccz[lab] = gz;
                    S.ccount[lab] = cnt;
                    S.ccls[lab + 1] = lci;
                }
                lab += 1;
                sx = (double)cix; sy = (double)ciy; sz = (double)ciz; cnt = 1;
                mcnt = 0;
            } else {
                sx += (double)cix; sy += (double)ciy; sz += (double)ciz; cnt += 1;
            }
            if (lane == 0) {
                S.order[mcnt] = sel;
                S.sdl[sel] = lab;
            }
            mcnt += 1;
            cls = lci;
            cx = cix; cy = ciy; cz = ciz;
            pn = norm3_xla(cx, cy, cz);
            __syncwarp();                    // order[] write -> next angle pass
        }
        // flush final cluster
        if (lane == 0) {
            float cf = (float)cnt;
            S.ccx[lab] = __fdiv_rn((float)sx, cf);
            S.ccy[lab] = __fdiv_rn((float)sy, cf);
            S.ccz[lab] = __fdiv_rn((float)sz, cf);
            S.ccount[lab] = cnt;
            S.bnc = lab;   // num_clusters (exclusive)
        }
    } else {
        // ================= candidate engine (warps 1..15, 480 threads) ========
        const int wtid = tid - 32;
        float mx[PER], my_[PER], mz_[PER], sreg[PER];
        int   ml[PER];
#pragma unroll
        for (int k = 0; k < PER; ++k) {
            int j = wtid + k * WT;
            bool v = (j < N) && (j != 0);    // j==0 starts visited
            mx[k]  = (j < N) ? S.px[j] : 0.0f;
            my_[k] = (j < N) ? S.py[j] : 0.0f;
            mz_[k] = (j < N) ? S.pz[j] : 0.0f;
            ml[k]  = v ? S.slbl[j] : -1;     // -1 == visited/invalid
        }

        int cls = S.slbl[0];
        float cx = S.px[0], cy = S.py[0], cz = S.pz[0];

        for (int step = 0; step < N - 1; ++step) {
            // ---- pass 1: branch-free squared-dist reductions ----
            unsigned minA = 0xFFFFFFFFu, minB = 0xFFFFFFFFu, maxAll = 0u;
#pragma unroll
            for (int k = 0; k < PER; ++k) {
                float dx = __fsub_rn(mx[k],  cx);
                float dy = __fsub_rn(my_[k], cy);
                float dz = __fsub_rn(mz_[k], cz);
                float s  = __fadd_rn(__fadd_rn(__fmul_rn(dx,dx), __fmul_rn(dy,dy)),
                                     __fmul_rn(dz,dz));
                sreg[k] = s;
                unsigned sb = __float_as_uint(s);    // s >= 0: bits ordered
                bool live = (ml[k] >= 0);
                bool isA  = (ml[k] == cls);
                minA   = min(minA,   isA             ? sb : 0xFFFFFFFFu);
                minB   = min(minB,   (live && !isA)  ? sb : 0xFFFFFFFFu);
                maxAll = max(maxAll, live            ? sb : 0u);
            }
            minA   = __reduce_min_sync(FULLMASK, minA);
            minB   = __reduce_min_sync(FULLMASK, minB);
            maxAll = __reduce_max_sync(FULLMASK, maxAll);
            if (lane == 0) {
                S.pminA[wid] = minA; S.pminB[wid] = minB; S.pmax[wid] = maxAll;
            }
            asm volatile("bar.sync 1, %0;" :: "r"(WT) : "memory");   // workers only

            // re-reduce the 15 worker partials (lanes 1..15)
            {
                bool ok = (lane >= 1 && lane < NWP);
                unsigned a = ok ? S.pminA[lane] : 0xFFFFFFFFu;
                unsigned b = ok ? S.pminB[lane] : 0xFFFFFFFFu;
                unsigned c = ok ? S.pmax[lane]  : 0u;
                minA   = __reduce_min_sync(FULLMASK, a);
                minB   = __reduce_min_sync(FULLMASK, b);
                maxAll = __reduce_max_sync(FULLMASK, c);
            }

            const bool hasA = (minA != 0xFFFFFFFFu), hasB = (minB != 0xFFFFFFFFu);
            const float dmin = __fsqrt_rn(__uint_as_float(min(minA, minB)));
            const float dmax = __fsqrt_rn(__uint_as_float(maxAll));
            const float Dn   = __fadd_rn(__fsub_rn(dmax, dmin), 1e-8f);

            // exact minimal costs per class (reference arithmetic on class-min d)
            float costA = INF_F, costB = INF_F;
            if (hasA) {
                float dA = __fsqrt_rn(__uint_as_float(minA));
                costA = __fdiv_rn(__fsub_rn(dA, dmin), Dn);        // + 0.0f exact
            }
            if (hasB) {
                float dB = __fsqrt_rn(__uint_as_float(minB));
                costB = __fadd_rn(__fdiv_rn(__fsub_rn(dB, dmin), Dn), 1.0f);
            }
            const float cstar = fminf(costA, costB);

            // conservative fp32 s-space admission thresholds (over-admit only)
            float thrSA = -1.0f, thrSB = -1.0f;
            if (hasA && costA == cstar) {
                float x = __fmul_ru(cstar, Dn);
                x = __fmul_ru(x, 1.000001f);
                x = __fadd_ru(x, 1e-37f);
                float dHi = __fmul_ru(__fadd_ru(dmin, x), 1.0000005f);
                thrSA = __fmul_ru(__fmul_ru(dHi, dHi), 1.0000005f);
            }
            if (hasB && costB == cstar) {
                float qHi = __fadd_ru(cstar, -1.0f);               // exact (Sterbenz)
                qHi = __fadd_ru(qHi, __fadd_ru(__fmul_ru(cstar, 3e-7f), 1e-37f));
                float x = __fmul_ru(qHi, Dn);
                x = __fmul_ru(x, 1.000001f);
                x = __fadd_ru(x, 1e-37f);
                float dHi = __fmul_ru(__fadd_ru(dmin, x), 1.0000005f);
                thrSB = __fmul_ru(__fmul_ru(dHi, dHi), 1.0000005f);
            }

            // ---- pass 2: filtered exact verification, min index ----
            unsigned best = 0xFFFFFFFFu;
#pragma unroll
            for (int k = 0; k < PER; ++k) {
                bool live = (ml[k] >= 0);
                bool isA  = (ml[k] == cls);
                float thr = isA ? thrSA : thrSB;
                if (live && sreg[k] <= thr) {
                    float d = __fsqrt_rn(sreg[k]);
                    float q = __fdiv_rn(__fsub_rn(d, dmin), Dn);
                    float c = isA ? q : __fadd_rn(q, 1.0f);
                    if (c == cstar) best = min(best, (unsigned)(wtid + k * WT));
                }
            }
            best = __reduce_min_sync(FULLMASK, best);
            if (lane == 0) S.psel[wid] = best;
            asm volatile("bar.sync 1, %0;" :: "r"(WT) : "memory");   // workers only

            int sel;
            {
                bool ok = (lane >= 1 && lane < NWP);
                unsigned v = ok ? S.psel[lane] : 0xFFFFFFFFu;
                sel = (int)__reduce_min_sync(FULLMASK, v);
            }

            // publish sel to the serial engine (one writer)
            if (tid == 32) ((volatile int*)S.selq)[step] = sel;

            // advance worker state
#pragma unroll
            for (int k = 0; k < PER; ++k)
                if (wtid + k * WT == sel) ml[k] = -1;     // mark visited
            cls = S.slbl[sel];
            cx = S.px[sel]; cy = S.py[sel]; cz = S.pz[sel];
        }
    }

    __syncthreads();    // join serial + candidate engines

    const int nc = S.bnc;

    // ---------------- stable descending sort by count (bitonic, 4096 keys) -----
    unsigned* skey = reinterpret_cast<unsigned*>(S.px);
    for (int i = tid; i < 4096; i += NT) {
        unsigned key = 0;
        if (i < nc) key = ((unsigned)S.ccount[i] << 12) | (4095u - (unsigned)i);
        skey[i] = key;
    }
    for (int i = tid; i < N; i += NT) { S.remap[i] = i; S.keep[i] = 1; }
    __syncthreads();

    for (int k = 2; k <= 4096; k <<= 1) {
        for (int j = k >> 1; j > 0; j >>= 1) {
#pragma unroll
            for (int e = 0; e < 8; ++e) {
                int i = tid + e * NT;
                int ixj = i ^ j;
                if (ixj > i) {
                    unsigned a2 = skey[i], b2 = skey[ixj];
                    bool descBlock = ((i & k) == 0);
                    if (descBlock ? (a2 < b2) : (a2 > b2)) { skey[i] = b2; skey[ixj] = a2; }
                }
            }
            __syncthreads();
        }
    }
    for (int i = tid; i < N; i += NT)
        if (i < nc) S.order[i] = 4095 - (int)(skey[i] & 4095u);
    __syncthreads();

    // ---------------- group order-positions by cluster class ----------
    if (wid < 10) {
        int c = wid, total = 0;
        int limit = (nc + 31) & ~31;
        for (int s = lane; s < limit; s += 32) {
            bool mm = (s < nc) && (S.ccls[S.order[s]] == c);
            unsigned bal = __ballot_sync(FULLMASK, mm);
            total += __popc(bal);
        }
        if (lane == 0) S.clsCount[c] = total;
    }
    __syncthreads();
    if (tid == 0) {
        int acc = 0;
        for (int c = 0; c < 10; ++c) { S.clsBase[c] = acc; acc += S.clsCount[c]; }
        S.clsBase[10] = acc;
    }
    __syncthreads();
    if (wid < 10) {
        int c = wid;
        int pos = S.clsBase[c];
        int limit = (nc + 31) & ~31;
        for (int s = lane; s < limit; s += 32) {
            bool mm = (s < nc) && (S.ccls[S.order[s]] == c);
            unsigned bal = __ballot_sync(FULLMASK, mm);
            if (mm) {
                int off = __popc(bal & ((1u << lane) - 1u));
                S.items[pos + off] = s;
            }
            pos += __popc(bal);
        }
    }
    __syncthreads();

    // ---------------- merge: independent per-class sequential chains ----------
    if (wid < 10) {
        int c    = wid;
        int base = S.clsBase[c];
        int len  = S.clsBase[c + 1] - base;
        float r2c = S.ar2[c];
        for (int t = 0; t < len; ++t) {
            __syncwarp();
            int ipos = S.items[base + t];
            if (!S.keep[ipos]) continue;
            int idx = S.order[ipos];
            float ax = S.ccx[idx], ay = S.ccy[idx], az = S.ccz[idx];
            for (int s = t + 1 + lane; s < len; s += 32) {
                int jpos = S.items[base + s];
                if (S.keep[jpos]) {
                    int jidx = S.order[jpos];
                    float dd = norm3_xla(__fsub_rn(S.ccx[jidx], ax),
                                         __fsub_rn(S.ccy[jidx], ay),
                                         __fsub_rn(S.ccz[jidx], az));
                    if (dd < r2c) {
                        S.keep[jpos]  = 0;
                        S.remap[jidx] = idx;
                    }
                }
            }
        }
    }
    __syncthreads();

    // ---------------- output (float32) ----------------
    for (int i = tid; i < N; i += NT)
        out[i] = (float)S.remap[S.sdl[i]];
}

extern "C" void kernel_launch(void* const* d_in, const int* in_sizes, int n_in,
                              void* d_out, int out_size)
{
    const float* pts     = nullptr;
    const int*   lbls    = nullptr;
    const float* anchors = nullptr;
    for (int i = 0; i < n_in; ++i) {
        if      (in_sizes[i] == N * 3) pts     = (const float*)d_in[i];
        else if (in_sizes[i] == N)     lbls    = (const int*)  d_in[i];
        else if (in_sizes[i] == 30)    anchors = (const float*)d_in[i];
    }
    if (!pts)     pts     = (const float*)d_in[0];
    if (!lbls)    lbls    = (const int*)  d_in[1];
    if (!anchors) anchors = (const float*)d_in[2];

    float* out = (float*)d_out;
    (void)out_size;

    static bool attr_done = false;
    if (!attr_done) {
        cudaFuncSetAttribute(frustum_cluster_kernel,
                             cudaFuncAttributeMaxDynamicSharedMemorySize,
                             (int)sizeof(Smem));
        attr_done = true;
    }
    frustum_cluster_kernel<<<1, NT, sizeof(Smem)>>>(pts, lbls, anchors, out);
}

// round 12
// speedup vs baseline: 5.0495x; 1.0026x over previous
#include <cuda_runtime.h>
#include <math.h>
#include <cstdint>

#define N    3072
#define NT   512
#define NWW  8       // worker warps (warps 1..8)
#define WT   256     // worker threads
#define PER  12      // N / WT exactly

#define ANGLE_THR_BITS 0x3FC90FDB   // f32(pi/2)
#define FULLMASK 0xffffffffu
#define INF_F  (__int_as_float(0x7f800000))

struct Smem {
    float px[N], py[N], pz[N];     // points (px reused as sort keys later)
    int   slbl[N];                 // per-point class
    int   sdl[N];                  // per-point cluster label
    float ccx[N], ccy[N], ccz[N];  // per-cluster centres
    int   ccount[N], ccls[N];      // per-cluster size / class
    int   order[N];                // scan: member list of current cluster; post: sort order
    int   items[N];                // post: class lists
    int   remap[N];                // post: merge remap
    int   selq[N];                 // sel sequence queue (workers -> warp 0)
    unsigned char keep[N];
    unsigned pminA[16], pminB[16], pmax[16], psel[16];
    float amdxy[10], amdz[10], ar2[10];
    int   clsCount[10], clsBase[11];
    int   bnc;
    float bval; unsigned ordb; int flag0;   // angle threshold data
};

__device__ __forceinline__ float norm3_xla(float x, float y, float z) {
    float s = __fadd_rn(__fadd_rn(__fmul_rn(x, x), __fmul_rn(y, y)), __fmul_rn(z, z));
    return __fsqrt_rn(s);
}
// XLA acos lowering: 2*atan2(sqrt(1-x*x), 1+x); pi at x==-1. Same libdevice atan2f
// as the reference -> bit-identical.
__device__ __forceinline__ float acos_xla(float x) {
    float s = __fsqrt_rn(__fsub_rn(1.0f, __fmul_rn(x, x)));
    float r = 2.0f * atan2f(s, __fadd_rn(1.0f, x));
    if (x == -1.0f) r = __int_as_float(0x40490FDB);
    return r;
}
__device__ __forceinline__ unsigned ford(float f) {
    unsigned u = __float_as_uint(f);
    return (u & 0x80000000u) ? ~u : (u | 0x80000000u);
}
__device__ __forceinline__ float ford_inv(unsigned o) {
    unsigned u = (o & 0x80000000u) ? (o ^ 0x80000000u) : ~o;
    return __uint_as_float(u);
}

__global__ void __launch_bounds__(NT, 1)
frustum_cluster_kernel(const float* __restrict__ pts,
                       const int*   __restrict__ lbl,
                       const float* __restrict__ anchors,
                       float* __restrict__ out)
{
    extern __shared__ char raw[];
    Smem& S = *reinterpret_cast<Smem*>(raw);

    const int tid  = threadIdx.x;
    const int wid  = tid >> 5;
    const int lane = tid & 31;
    const float THR = __int_as_float(ANGLE_THR_BITS);

    // ---------------- init ----------------
    for (int j = tid; j < N; j += NT) {
        S.px[j]   = pts[3*j + 0];
        S.py[j]   = pts[3*j + 1];
        S.pz[j]   = pts[3*j + 2];
        S.slbl[j] = lbl[j];
        S.selq[j] = -1;
    }
    if (tid < 10) {
        float l = anchors[tid*3+0], w = anchors[tid*3+1], h = anchors[tid*3+2];
        S.amdxy[tid] = fmaxf(l, w);
        S.amdz[tid]  = h;
        S.ar2[tid]   = __fdiv_rn(norm3_xla(l, w, h), 2.0f);
    }
    if (tid == 0) {
        S.sdl[0]   = 0;
        S.ccls[0]  = lbl[0];
        S.order[0] = 0;                      // member list = {0}
        // binary search: largest x with acos_xla(x) >= THR
        unsigned lo = ford(-1.0f), hi = ford(1.0f);
        while (hi - lo > 1u) {
            unsigned mid = lo + ((hi - lo) >> 1);
            if (acos_xla(ford_inv(mid)) >= THR) lo = mid; else hi = mid;
        }
        S.bval  = ford_inv(lo);
        S.ordb  = lo;
        S.flag0 = (acos_xla(0.0f) < THR) ? 1 : 0;
    }
    __syncthreads();

    if (wid == 0) {
        // ================= serial engine (warp 0): trails the workers =========
        const float    bval  = S.bval;
        const unsigned ordb  = S.ordb;
        const int      flag0 = S.flag0;
        volatile int*  vq    = S.selq;

        int   cls = S.slbl[0];
        float cx = S.px[0], cy = S.py[0], cz = S.pz[0];
        float pn = norm3_xla(cx, cy, cz);
        int    lab = 0, cnt = 1, mcnt = 1;
        double sx = (double)cx, sy = (double)cy, sz = (double)cz;

        for (int step = 0; step < N - 1; ++step) {
            // ---- angle pass over current member list (independent of sel) ----
            unsigned xmb = 0xFFFFFFFFu;
            for (int i = lane; i < mcnt; i += 32) {
                int j = S.order[i];
                float dx = __fsub_rn(S.px[j], cx);
                float dy = __fsub_rn(S.py[j], cy);
                float dz = __fsub_rn(S.pz[j], cz);
                float d  = norm3_xla(dx, dy, dz);
                float dt = -(__fadd_rn(__fadd_rn(__fmul_rn(cx,dx), __fmul_rn(cy,dy)),
                                       __fmul_rn(cz,dz)));
                float den = __fadd_rn(__fmul_rn(pn, d), 1e-8f);
                xmb = min(xmb, ford(__fdiv_rn(dt, den)));
            }
            xmb = __reduce_min_sync(FULLMASK, xmb);
            float xc = fminf(fmaxf(ford_inv(xmb), -1.0f), 1.0f);
            bool angflag;
            if (xc == 0.0f) {
                angflag = (flag0 != 0);
            } else {
                long dlt = (long)ford(xc) - (long)ordb;
                if (dlt > -65536 && dlt < 65536) angflag = (acos_xla(xc) < THR);
                else                             angflag = (xc > bval);
            }

            // ---- consume sel from the queue (workers run ahead) ----
            int sel;
            for (;;) {
                sel = vq[step];
                if (sel >= 0) break;
                __nanosleep(40);
            }

            // ---- tail decision + cluster state ----
            float cix = S.px[sel], ciy = S.py[sel], ciz = S.pz[sel];
            int   lci = S.slbl[sel];
            float ddx = __fsub_rn(cx, cix);
            float ddy = __fsub_rn(cy, ciy);
            float ddz = __fsub_rn(cz, ciz);
            float dn = norm3_xla(ddx, ddy, ddz);
            float cf = (float)cnt;
            float gx = __fdiv_rn((float)sx, cf);
            float gy = __fdiv_rn((float)sy, cf);
            float gz = __fdiv_rn((float)sz, cf);
            float en = norm3_xla(__fsub_rn(gx, cix), __fsub_rn(gy, ciy),
                                 __fsub_rn(gz, ciz));
            float a0 = S.amdxy[cls], a2 = S.amdz[cls], r2 = S.ar2[cls];
            bool newc = (fabsf(ddx) > a0) | (fabsf(ddy) > a0) | (fabsf(ddz) > a2) |
                        angflag | (lci != cls) | (dn > r2) | (en > r2);
            if (newc) {
                if (lane == 0) {
                    S.ccx[lab] = gx; S.ccy[lab] = gy; S.ccz[lab] = gz;
                    S.ccount[lab] = cnt;
                    S.ccls[lab + 1] = lci;
                }
                lab += 1;
                sx = (double)cix; sy = (double)ciy; sz = (double)ciz; cnt = 1;
                mcnt = 0;
            } else {
                sx += (double)cix; sy += (double)ciy; sz += (double)ciz; cnt += 1;
            }
            if (lane == 0) {
                S.order[mcnt] = sel;
                S.sdl[sel] = lab;
            }
            mcnt += 1;
            cls = lci;
            cx = cix; cy = ciy; cz = ciz;
            pn = norm3_xla(cx, cy, cz);
            __syncwarp();                    // order[] write -> next angle pass
        }
        // flush final cluster
        if (lane == 0) {
            float cf = (float)cnt;
            S.ccx[lab] = __fdiv_rn((float)sx, cf);
            S.ccy[lab] = __fdiv_rn((float)sy, cf);
            S.ccz[lab] = __fdiv_rn((float)sz, cf);
            S.ccount[lab] = cnt;
            S.bnc = lab;   // num_clusters (exclusive)
        }
    } else if (wid <= NWW) {
        // ================= candidate engine (warps 1..8, 256 threads) =========
        const int wtid = tid - 32;           // 0..255
        float mx[PER], my_[PER], mz_[PER], sreg[PER];
        int   ml[PER];
#pragma unroll
        for (int k = 0; k < PER; ++k) {
            int j = wtid + (k << 8);         // covers 0..3071 exactly
            mx[k]  = S.px[j];
            my_[k] = S.py[j];
            mz_[k] = S.pz[j];
            ml[k]  = (j == 0) ? -1 : S.slbl[j];   // -1 == visited
        }

        int cls = S.slbl[0];
        float cx = S.px[0], cy = S.py[0], cz = S.pz[0];

        for (int step = 0; step < N - 1; ++step) {
            // ---- pass 1: branch-free squared-dist reductions ----
            unsigned minA = 0xFFFFFFFFu, minB = 0xFFFFFFFFu, maxAll = 0u;
#pragma unroll
            for (int k = 0; k < PER; ++k) {
                float dx = __fsub_rn(mx[k],  cx);
                float dy = __fsub_rn(my_[k], cy);
                float dz = __fsub_rn(mz_[k], cz);
                float s  = __fadd_rn(__fadd_rn(__fmul_rn(dx,dx), __fmul_rn(dy,dy)),
                                     __fmul_rn(dz,dz));
                sreg[k] = s;
                unsigned sb = __float_as_uint(s);    // s >= 0: bits ordered
                bool live = (ml[k] >= 0);
                bool isA  = (ml[k] == cls);
                minA   = min(minA,   isA             ? sb : 0xFFFFFFFFu);
                minB   = min(minB,   (live && !isA)  ? sb : 0xFFFFFFFFu);
                maxAll = max(maxAll, live            ? sb : 0u);
            }
            minA   = __reduce_min_sync(FULLMASK, minA);
            minB   = __reduce_min_sync(FULLMASK, minB);
            maxAll = __reduce_max_sync(FULLMASK, maxAll);
            if (lane == 0) {
                S.pminA[wid] = minA; S.pminB[wid] = minB; S.pmax[wid] = maxAll;
            }
            asm volatile("bar.sync 1, %0;" :: "r"(WT) : "memory");   // workers only

            // re-reduce the 8 worker partials (lanes 1..8)
            {
                bool ok = (lane >= 1 && lane <= NWW);
                unsigned a = ok ? S.pminA[lane] : 0xFFFFFFFFu;
                unsigned b = ok ? S.pminB[lane] : 0xFFFFFFFFu;
                unsigned c = ok ? S.pmax[lane]  : 0u;
                minA   = __reduce_min_sync(FULLMASK, a);
                minB   = __reduce_min_sync(FULLMASK, b);
                maxAll = __reduce_max_sync(FULLMASK, c);
            }

            const bool hasA = (minA != 0xFFFFFFFFu), hasB = (minB != 0xFFFFFFFFu);
            // dA/dB/dmax sqrts run in parallel; dmin = min of sqrts (exact:
            // sqrt_rn is monotone, so min(sqrt) == sqrt(min); fminf drops NaN).
            const float dA   = __fsqrt_rn(__uint_as_float(minA));   // NaN if !hasA
            const float dB   = __fsqrt_rn(__uint_as_float(minB));   // NaN if !hasB
            const float dmax = __fsqrt_rn(__uint_as_float(maxAll));
            const float dmin = fminf(dA, dB);
            const float Dn   = __fadd_rn(__fsub_rn(dmax, dmin), 1e-8f);

            // exact minimal costs per class (reference arithmetic on class-min d)
            float costA = INF_F, costB = INF_F;
            if (hasA) costA = __fdiv_rn(__fsub_rn(dA, dmin), Dn);   // + 0.0f exact
            if (hasB) costB = __fadd_rn(__fdiv_rn(__fsub_rn(dB, dmin), Dn), 1.0f);
            const float cstar = fminf(costA, costB);

            // conservative fp32 s-space admission thresholds (over-admit only)
            float thrSA = -1.0f, thrSB = -1.0f;
            if (hasA && costA == cstar) {
                float x = __fmul_ru(cstar, Dn);
                x = __fmul_ru(x, 1.000001f);
                x = __fadd_ru(x, 1e-37f);
                float dHi = __fmul_ru(__fadd_ru(dmin, x), 1.0000005f);
                thrSA = __fmul_ru(__fmul_ru(dHi, dHi), 1.0000005f);
            }
            if (hasB && costB == cstar) {
                float qHi = __fadd_ru(cstar, -1.0f);               // exact (Sterbenz)
                qHi = __fadd_ru(qHi, __fadd_ru(__fmul_ru(cstar, 3e-7f), 1e-37f));
                float x = __fmul_ru(qHi, Dn);
                x = __fmul_ru(x, 1.000001f);
                x = __fadd_ru(x, 1e-37f);
                float dHi = __fmul_ru(__fadd_ru(dmin, x), 1.0000005f);
                thrSB = __fmul_ru(__fmul_ru(dHi, dHi), 1.0000005f);
            }

            // ---- pass 2: filtered exact verification, min index ----
            unsigned best = 0xFFFFFFFFu;
#pragma unroll
            for (int k = 0; k < PER; ++k) {
                bool live = (ml[k] >= 0);
                bool isA  = (ml[k] == cls);
                float thr = isA ? thrSA : thrSB;
                if (live && sreg[k] <= thr) {
                    float d = __fsqrt_rn(sreg[k]);
                    float q = __fdiv_rn(__fsub_rn(d, dmin), Dn);
                    float c = isA ? q : __fadd_rn(q, 1.0f);
                    if (c == cstar) best = min(best, (unsigned)(wtid + (k << 8)));
                }
            }
            best = __reduce_min_sync(FULLMASK, best);
            if (lane == 0) S.psel[wid] = best;
            asm volatile("bar.sync 1, %0;" :: "r"(WT) : "memory");   // workers only

            int sel;
            {
                bool ok = (lane >= 1 && lane <= NWW);
                unsigned v = ok ? S.psel[lane] : 0xFFFFFFFFu;
                sel = (int)__reduce_min_sync(FULLMASK, v);
            }

            // publish sel to the serial engine (one writer)
            if (tid == 32) ((volatile int*)S.selq)[step] = sel;

            // advance worker state
#pragma unroll
            for (int k = 0; k < PER; ++k)
                if (wtid + (k << 8) == sel) ml[k] = -1;     // mark visited
            cls = S.slbl[sel];
            cx = S.px[sel]; cy = S.py[sel]; cz = S.pz[sel];
        }
    }
    // warps 9..15 fall through directly to the join barrier

    __syncthreads();    // join serial + candidate engines (+ idle warps)

    const int nc = S.bnc;

    // ---------------- stable descending sort by count (bitonic, 4096 keys) -----
    unsigned* skey = reinterpret_cast<unsigned*>(S.px);
    for (int i = tid; i < 4096; i += NT) {
        unsigned key = 0;
        if (i < nc) key = ((unsigned)S.ccount[i] << 12) | (4095u - (unsigned)i);
        skey[i] = key;
    }
    for (int i = tid; i < N; i += NT) { S.remap[i] = i; S.keep[i] = 1; }
    __syncthreads();

    for (int k = 2; k <= 4096; k <<= 1) {
        for (int j = k >> 1; j > 0; j >>= 1) {
#pragma unroll
            for (int e = 0; e < 8; ++e) {
                int i = tid + e * NT;
                int ixj = i ^ j;
                if (ixj > i) {
                    unsigned a2 = skey[i], b2 = skey[ixj];
                    bool descBlock = ((i & k) == 0);
                    if (descBlock ? (a2 < b2) : (a2 > b2)) { skey[i] = b2; skey[ixj] = a2; }
                }
            }
            __syncthreads();
        }
    }
    for (int i = tid; i < N; i += NT)
        if (i < nc) S.order[i] = 4095 - (int)(skey[i] & 4095u);
    __syncthreads();

    // ---------------- group order-positions by cluster class ----------
    if (wid < 10) {
        int c = wid, total = 0;
        int limit = (nc + 31) & ~31;
        for (int s = lane; s < limit; s += 32) {
            bool mm = (s < nc) && (S.ccls[S.order[s]] == c);
            unsigned bal = __ballot_sync(FULLMASK, mm);
            total += __popc(bal);
        }
        if (lane == 0) S.clsCount[c] = total;
    }
    __syncthreads();
    if (tid == 0) {
        int acc = 0;
        for (int c = 0; c < 10; ++c) { S.clsBase[c] = acc; acc += S.clsCount[c]; }
        S.clsBase[10] = acc;
    }
    __syncthreads();
    if (wid < 10) {
        int c = wid;
        int pos = S.clsBase[c];
        int limit = (nc + 31) & ~31;
        for (int s = lane; s < limit; s += 32) {
            bool mm = (s < nc) && (S.ccls[S.order[s]] == c);
            unsigned bal = __ballot_sync(FULLMASK, mm);
            if (mm) {
                int off = __popc(bal & ((1u << lane) - 1u));
                S.items[pos + off] = s;
            }
            pos += __popc(bal);
        }
    }
    __syncthreads();

    // ---------------- merge: independent per-class sequential chains ----------
    if (wid < 10) {
        int c    = wid;
        int base = S.clsBase[c];
        int len  = S.clsBase[c + 1] - base;
        float r2c = S.ar2[c];
        for (int t = 0; t < len; ++t) {
            __syncwarp();
            int ipos = S.items[base + t];
            if (!S.keep[ipos]) continue;
            int idx = S.order[ipos];
            float ax = S.ccx[idx], ay = S.ccy[idx], az = S.ccz[idx];
            for (int s = t + 1 + lane; s < len; s += 32) {
                int jpos = S.items[base + s];
                if (S.keep[jpos]) {
                    int jidx = S.order[jpos];
                    float dd = norm3_xla(__fsub_rn(S.ccx[jidx], ax),
                                         __fsub_rn(S.ccy[jidx], ay),
                                         __fsub_rn(S.ccz[jidx], az));
                    if (dd < r2c) {
                        S.keep[jpos]  = 0;
                        S.remap[jidx] = idx;
                    }
                }
            }
        }
    }
    __syncthreads();

    // ---------------- output (float32) ----------------
    for (int i = tid; i < N; i += NT)
        out[i] = (float)S.remap[S.sdl[i]];
}

extern "C" void kernel_launch(void* const* d_in, const int* in_sizes, int n_in,
                              void* d_out, int out_size)
{
    const float* pts     = nullptr;
    const int*   lbls    = nullptr;
    const float* anchors = nullptr;
    for (int i = 0; i < n_in; ++i) {
        if      (in_sizes[i] == N * 3) pts     = (const float*)d_in[i];
        else if (in_sizes[i] == N)     lbls    = (const int*)  d_in[i];
        else if (in_sizes[i] == 30)    anchors = (const float*)d_in[i];
    }
    if (!pts)     pts     = (const float*)d_in[0];
    if (!lbls)    lbls    = (const int*)  d_in[1];
    if (!anchors) anchors = (const float*)d_in[2];

    float* out = (float*)d_out;
    (void)out_size;

    static bool attr_done = false;
    if (!attr_done) {
        cudaFuncSetAttribute(frustum_cluster_kernel,
                             cudaFuncAttributeMaxDynamicSharedMemorySize,
                             (int)sizeof(Smem));
        attr_done = true;
    }
    frustum_cluster_kernel<<<1, NT, sizeof(Smem)>>>(pts, lbls, anchors, out);
}

// round 14
// speedup vs baseline: 5.8952x; 1.1675x over previous
#include <cuda_runtime.h>
#include <math.h>
#include <cstdint>

#define N    3072
#define NT   512
#define NWW  8       // worker warps (warps 1..8)
#define WT   256     // worker threads
#define PER  12      // N / WT exactly
#define NPAIR 6      // PER/2

#define ANGLE_THR_BITS 0x3FC90FDB   // f32(pi/2)
#define FULLMASK 0xffffffffu
#define INF_F  (__int_as_float(0x7f800000))
#define INFB   0x7f800000u

struct Smem {
    float px[N], py[N], pz[N];     // points (px reused as sort keys later)
    int   slbl[N];                 // per-point class
    int   sdl[N];                  // per-point cluster label
    float ccx[N], ccy[N], ccz[N];  // per-cluster centres
    int   ccount[N], ccls[N];      // per-cluster size / class
    int   order[N];                // scan: member list; post: sort order
    int   items[N];                // post: class lists
    int   remap[N];                // post: merge remap
    int   selq[N];                 // sel sequence queue (workers -> warp 0)
    unsigned char keep[N];
    unsigned p1A[16], pIdxA[16], p2A[16], p1B[16], pMax[16], psel[16];
    float amdxy[10], amdz[10], ar2[10];
    int   clsCount[10], clsBase[11];
    int   bnc;
    float bval; unsigned ordb; int flag0;   // angle threshold data
};

__device__ __forceinline__ float norm3_xla(float x, float y, float z) {
    float s = __fadd_rn(__fadd_rn(__fmul_rn(x, x), __fmul_rn(y, y)), __fmul_rn(z, z));
    return __fsqrt_rn(s);
}
// XLA acos lowering: 2*atan2(sqrt(1-x*x), 1+x); pi at x==-1. Same libdevice atan2f
// as the reference -> bit-identical.
__device__ __forceinline__ float acos_xla(float x) {
    float s = __fsqrt_rn(__fsub_rn(1.0f, __fmul_rn(x, x)));
    float r = 2.0f * atan2f(s, __fadd_rn(1.0f, x));
    if (x == -1.0f) r = __int_as_float(0x40490FDB);
    return r;
}
__device__ __forceinline__ unsigned ford(float f) {
    unsigned u = __float_as_uint(f);
    return (u & 0x80000000u) ? ~u : (u | 0x80000000u);
}
__device__ __forceinline__ float ford_inv(unsigned o) {
    unsigned u = (o & 0x80000000u) ? (o ^ 0x80000000u) : ~o;
    return __uint_as_float(u);
}

// packed f32x2 helpers (two independent IEEE-RN f32 ops per instruction)
__device__ __forceinline__ unsigned long long packf2(float lo, float hi) {
    unsigned long long r;
    asm("mov.b64 %0, {%1, %2};" : "=l"(r) : "f"(lo), "f"(hi));
    return r;
}
__device__ __forceinline__ void unpackf2(unsigned long long p, float& lo, float& hi) {
    asm("mov.b64 {%0, %1}, %2;" : "=f"(lo), "=f"(hi) : "l"(p));
}
__device__ __forceinline__ unsigned long long addf2(unsigned long long a, unsigned long long b) {
    unsigned long long r;
    asm("add.rn.f32x2 %0, %1, %2;" : "=l"(r) : "l"(a), "l"(b));
    return r;
}
__device__ __forceinline__ unsigned long long mulf2(unsigned long long a, unsigned long long b) {
    unsigned long long r;
    asm("mul.rn.f32x2 %0, %1, %2;" : "=l"(r) : "l"(a), "l"(b));
    return r;
}

__global__ void __launch_bounds__(NT, 1)
frustum_cluster_kernel(const float* __restrict__ pts,
                       const int*   __restrict__ lbl,
                       const float* __restrict__ anchors,
                       float* __restrict__ out)
{
    extern __shared__ char raw[];
    Smem& S = *reinterpret_cast<Smem*>(raw);

    const int tid  = threadIdx.x;
    const int wid  = tid >> 5;
    const int lane = tid & 31;
    const float THR = __int_as_float(ANGLE_THR_BITS);

    // ---------------- init ----------------
    for (int j = tid; j < N; j += NT) {
        S.px[j]   = pts[3*j + 0];
        S.py[j]   = pts[3*j + 1];
        S.pz[j]   = pts[3*j + 2];
        S.slbl[j] = lbl[j];
        S.selq[j] = -1;
    }
    if (tid < 10) {
        float l = anchors[tid*3+0], w = anchors[tid*3+1], h = anchors[tid*3+2];
        S.amdxy[tid] = fmaxf(l, w);
        S.amdz[tid]  = h;
        S.ar2[tid]   = __fdiv_rn(norm3_xla(l, w, h), 2.0f);
    }
    if (tid == 0) {
        S.sdl[0]   = 0;
        S.ccls[0]  = lbl[0];
        S.order[0] = 0;                      // member list = {0}
        // binary search: largest x with acos_xla(x) >= THR
        unsigned lo = ford(-1.0f), hi = ford(1.0f);
        while (hi - lo > 1u) {
            unsigned mid = lo + ((hi - lo) >> 1);
            if (acos_xla(ford_inv(mid)) >= THR) lo = mid; else hi = mid;
        }
        S.bval  = ford_inv(lo);
        S.ordb  = lo;
        S.flag0 = (acos_xla(0.0f) < THR) ? 1 : 0;
    }
    __syncthreads();

    if (wid == 0) {
        // ================= serial engine (warp 0): trails the workers =========
        const float    bval  = S.bval;
        const unsigned ordb  = S.ordb;
        const int      flag0 = S.flag0;
        volatile int*  vq    = S.selq;

        int   cls = S.slbl[0];
        float cx = S.px[0], cy = S.py[0], cz = S.pz[0];
        float pn = norm3_xla(cx, cy, cz);
        int    lab = 0, cnt = 1, mcnt = 1;
        double sx = (double)cx, sy = (double)cy, sz = (double)cz;

        for (int step = 0; step < N - 1; ++step) {
            // ---- angle pass over current member list (independent of sel) ----
            unsigned xmb = 0xFFFFFFFFu;
            for (int i = lane; i < mcnt; i += 32) {
                int j = S.order[i];
                float dx = __fsub_rn(S.px[j], cx);
                float dy = __fsub_rn(S.py[j], cy);
                float dz = __fsub_rn(S.pz[j], cz);
                float d  = norm3_xla(dx, dy, dz);
                float dt = -(__fadd_rn(__fadd_rn(__fmul_rn(cx,dx), __fmul_rn(cy,dy)),
                                       __fmul_rn(cz,dz)));
                float den = __fadd_rn(__fmul_rn(pn, d), 1e-8f);
                xmb = min(xmb, ford(__fdiv_rn(dt, den)));
            }
            xmb = __reduce_min_sync(FULLMASK, xmb);
            float xc = fminf(fmaxf(ford_inv(xmb), -1.0f), 1.0f);
            bool angflag;
            if (xc == 0.0f) {
                angflag = (flag0 != 0);
            } else {
                long dlt = (long)ford(xc) - (long)ordb;
                if (dlt > -65536 && dlt < 65536) angflag = (acos_xla(xc) < THR);
                else                             angflag = (xc > bval);
            }

            // ---- consume sel from the queue (workers run ahead) ----
            int sel;
            for (;;) {
                sel = vq[step];
                if (sel >= 0) break;
                __nanosleep(40);
            }

            // ---- tail decision + cluster state ----
            float cix = S.px[sel], ciy = S.py[sel], ciz = S.pz[sel];
            int   lci = S.slbl[sel];
            float ddx = __fsub_rn(cx, cix);
            float ddy = __fsub_rn(cy, ciy);
            float ddz = __fsub_rn(cz, ciz);
            float dn = norm3_xla(ddx, ddy, ddz);
            float cf = (float)cnt;
            float gx = __fdiv_rn((float)sx, cf);
            float gy = __fdiv_rn((float)sy, cf);
            float gz = __fdiv_rn((float)sz, cf);
            float en = norm3_xla(__fsub_rn(gx, cix), __fsub_rn(gy, ciy),
                                 __fsub_rn(gz, ciz));
            float a0 = S.amdxy[cls], a2 = S.amdz[cls], r2 = S.ar2[cls];
            bool newc = (fabsf(ddx) > a0) | (fabsf(ddy) > a0) | (fabsf(ddz) > a2) |
                        angflag | (lci != cls) | (dn > r2) | (en > r2);
            if (newc) {
                if (lane == 0) {
                    S.ccx[lab] = gx; S.ccy[lab] = gy; S.ccz[lab] = gz;
                    S.ccount[lab] = cnt;
                    S.ccls[lab + 1] = lci;
                }
                lab += 1;
                sx = (double)cix; sy = (double)ciy; sz = (double)ciz; cnt = 1;
                mcnt = 0;
            } else {
                sx += (double)cix; sy += (double)ciy; sz += (double)ciz; cnt += 1;
            }
            if (lane == 0) {
                S.order[mcnt] = sel;
                S.sdl[sel] = lab;
            }
            mcnt += 1;
            cls = lci;
            cx = cix; cy = ciy; cz = ciz;
            pn = norm3_xla(cx, cy, cz);
            __syncwarp();                    // order[] write -> next angle pass
        }
        // flush final cluster
        if (lane == 0) {
            float cf = (float)cnt;
            S.ccx[lab] = __fdiv_rn((float)sx, cf);
            S.ccy[lab] = __fdiv_rn((float)sy, cf);
            S.ccz[lab] = __fdiv_rn((float)sz, cf);
            S.ccount[lab] = cnt;
            S.bnc = lab;   // num_clusters (exclusive)
        }
    } else if (wid <= NWW) {
        // ================= candidate engine (warps 1..8, 256 threads) =========
        const int wtid = tid - 32;           // 0..255
        unsigned long long mxp[NPAIR], myp[NPAIR], mzp[NPAIR];
        int ml[PER];
#pragma unroll
        for (int k = 0; k < NPAIR; ++k) {
            int j0 = wtid + ((2*k)     << 8);
            int j1 = wtid + ((2*k + 1) << 8);
            mxp[k] = packf2(S.px[j0], S.px[j1]);
            myp[k] = packf2(S.py[j0], S.py[j1]);
            mzp[k] = packf2(S.pz[j0], S.pz[j1]);
            ml[2*k]   = (j0 == 0) ? -1 : S.slbl[j0];
            ml[2*k+1] = S.slbl[j1];
        }

        int cls = S.slbl[0];
        float cx = S.px[0], cy = S.py[0], cz = S.pz[0];

        for (int step = 0; step < N - 1; ++step) {
            unsigned long long ncxp = packf2(-cx, -cx);
            unsigned long long ncyp = packf2(-cy, -cy);
            unsigned long long nczp = packf2(-cz, -cz);

            // ---- pass 1: packed dists; minA(+idx,+min2), minB, max ----
            float m1A = INF_F, m2A = INF_F, m1B = INF_F;
            unsigned maxb = 0u;               // unsigned-0 sentinel (s >= 0)
            unsigned idxA = 0xFFFFFFFFu;
#pragma unroll
            for (int k = 0; k < NPAIR; ++k) {
                unsigned long long dxp = addf2(mxp[k], ncxp);
                unsigned long long dyp = addf2(myp[k], ncyp);
                unsigned long long dzp = addf2(mzp[k], nczp);
                unsigned long long sp  = addf2(addf2(mulf2(dxp,dxp), mulf2(dyp,dyp)),
                                               mulf2(dzp,dzp));
                float s0, s1;
                unpackf2(sp, s0, s1);
#pragma unroll
                for (int h = 0; h < 2; ++h) {
                    float s = (h == 0) ? s0 : s1;
                    int   l = ml[2*k + h];
                    unsigned idx = (unsigned)(wtid + ((2*k + h) << 8));
                    bool isA  = (l == cls);
                    bool live = (l >= 0);
                    float sA  = isA ? s : INF_F;
                    float sNL = isA ? INF_F : s;
                    float sB  = live ? sNL : INF_F;
                    maxb = max(maxb, live ? __float_as_uint(s) : 0u);
                    bool lt = (sA < m1A);
                    idxA = lt ? idx : idxA;
                    m2A  = fminf(m2A, fmaxf(m1A, sA));
                    m1A  = fminf(m1A, sA);
                    m1B  = fminf(m1B, sB);
                }
            }
            // warp-level combine
            unsigned b1A = __reduce_min_sync(FULLMASK, __float_as_uint(m1A));
            unsigned bi  = (__float_as_uint(m1A) == b1A) ? idxA : 0xFFFFFFFFu;
            unsigned bIdxA = __reduce_min_sync(FULLMASK, bi);
            {   // warp second-min with duplicate handling
                unsigned eq  = __ballot_sync(FULLMASK, __float_as_uint(m1A) == b1A);
                unsigned c2  = (__float_as_uint(m1A) == b1A) ? __float_as_uint(m2A)
                                                             : __float_as_uint(m1A);
                unsigned b2A = __reduce_min_sync(FULLMASK, c2);
                if (__popc(eq) >= 2) b2A = b1A;
                unsigned b1B = __reduce_min_sync(FULLMASK, __float_as_uint(m1B));
                unsigned bMx = __reduce_max_sync(FULLMASK, maxb);
                if (lane == 0) {
                    S.p1A[wid] = b1A; S.pIdxA[wid] = bIdxA; S.p2A[wid] = b2A;
                    S.p1B[wid] = b1B; S.pMax[wid] = bMx;
                }
            }
            asm volatile("bar.sync 1, %0;" :: "r"(WT) : "memory");   // THE barrier

            // cross-warp combine (all workers, redundant -> identical results)
            unsigned g1A, gIdxA, g2A, g1B, gMx;
            {
                bool ok = (lane >= 1 && lane <= NWW);
                unsigned r1 = ok ? S.p1A[lane]  : INFB;
                unsigned ri = ok ? S.pIdxA[lane]: 0xFFFFFFFFu;
                unsigned r2 = ok ? S.p2A[lane]  : INFB;
                unsigned rb = ok ? S.p1B[lane]  : INFB;
                unsigned rm = ok ? S.pMax[lane] : 0u;
                g1A = __reduce_min_sync(FULLMASK, r1);
                gIdxA = __reduce_min_sync(FULLMASK,
                            (ok && r1 == g1A) ? ri : 0xFFFFFFFFu);
                unsigned eq = __ballot_sync(FULLMASK, ok && r1 == g1A);
                unsigned c2 = ok ? ((r1 == g1A) ? r2 : r1) : INFB;
                g2A = __reduce_min_sync(FULLMASK, c2);
                if (__popc(eq) >= 2) g2A = g1A;
                g1B = __reduce_min_sync(FULLMASK, rb);
                gMx = __reduce_max_sync(FULLMASK, rm);
            }

            const bool hasA = (g1A != INFB), hasB = (g1B != INFB);
            const float dA   = __fsqrt_rn(__uint_as_float(g1A));  // inf if !hasA
            const float dB   = __fsqrt_rn(__uint_as_float(g1B));  // inf if !hasB
            const float dmax = __fsqrt_rn(__uint_as_float(gMx));
            const float dmin = fminf(dA, dB);
            const float Dn   = __fadd_rn(__fsub_rn(dmax, dmin), 1e-8f);

            float costA = INF_F;
            if (hasA) costA = __fdiv_rn(__fsub_rn(dA, dmin), Dn);  // + 0.0f exact

            int sel = -1;
            bool fast = false;
            if (hasA && costA < 1.0f) {
                // conservative s-space admission threshold for class A (over-admit)
                float x = __fmul_ru(costA, Dn);
                x = __fmul_ru(x, 1.000001f);
                x = __fadd_ru(x, 1e-37f);
                float dHi = __fmul_ru(__fadd_ru(dmin, x), 1.0000005f);
                float thrSA = __fmul_ru(__fmul_ru(dHi, dHi), 1.0000005f);
                // fast iff no candidate besides s==g1A can be admitted
                if (thrSA < __uint_as_float(g2A)) { fast = true; sel = (int)gIdxA; }
            }

            if (!fast) {
                // ---- slow path (rare, block-uniform): full generic logic ----
                float costB = INF_F;
                if (hasB) costB = __fadd_rn(__fdiv_rn(__fsub_rn(dB, dmin), Dn), 1.0f);
                float costA2 = hasA ? costA : INF_F;
                float cstar = fminf(costA2, costB);
                float thrSA = -1.0f, thrSB = -1.0f;
                if (hasA && costA2 == cstar) {
                    float x = __fmul_ru(cstar, Dn);
                    x = __fmul_ru(x, 1.000001f);
                    x = __fadd_ru(x, 1e-37f);
                    float dHi = __fmul_ru(__fadd_ru(dmin, x), 1.0000005f);
                    thrSA = __fmul_ru(__fmul_ru(dHi, dHi), 1.0000005f);
                }
                if (hasB && costB == cstar) {
                    float qHi = __fadd_ru(cstar, -1.0f);           // exact (Sterbenz)
                    qHi = __fadd_ru(qHi, __fadd_ru(__fmul_ru(cstar, 3e-7f), 1e-37f));
                    float x = __fmul_ru(qHi, Dn);
                    x = __fmul_ru(x, 1.000001f);
                    x = __fadd_ru(x, 1e-37f);
                    float dHi = __fmul_ru(__fadd_ru(dmin, x), 1.0000005f);
                    thrSB = __fmul_ru(__fmul_ru(dHi, dHi), 1.0000005f);
                }
                unsigned best = 0xFFFFFFFFu;
#pragma unroll
                for (int k = 0; k < NPAIR; ++k) {
                    unsigned long long dxp = addf2(mxp[k], ncxp);
                    unsigned long long dyp = addf2(myp[k], ncyp);
                    unsigned long long dzp = addf2(mzp[k], nczp);
                    unsigned long long sp  = addf2(addf2(mulf2(dxp,dxp),
                                                         mulf2(dyp,dyp)),
                                                   mulf2(dzp,dzp));
                    float s0, s1;
                    unpackf2(sp, s0, s1);
#pragma unroll
                    for (int h = 0; h < 2; ++h) {
                        float s = (h == 0) ? s0 : s1;
                        int   l = ml[2*k + h];
                        bool live = (l >= 0);
                        bool isA  = (l == cls);
                        float thr = isA ? thrSA : thrSB;
                        if (live && s <= thr) {
                            float d = __fsqrt_rn(s);
                            float q = __fdiv_rn(__fsub_rn(d, dmin), Dn);
                            float c = isA ? q : __fadd_rn(q, 1.0f);
                            if (c == cstar)
                                best = min(best, (unsigned)(wtid + ((2*k + h) << 8)));
                        }
                    }
                }
                best = __reduce_min_sync(FULLMASK, best);
                if (lane == 0) S.psel[wid] = best;
                asm volatile("bar.sync 1, %0;" :: "r"(WT) : "memory");
                {
                    bool ok = (lane >= 1 && lane <= NWW);
                    unsigned v = ok ? S.psel[lane] : 0xFFFFFFFFu;
                    sel = (int)__reduce_min_sync(FULLMASK, v);
                }
                if (sel < 0) sel = (int)gIdxA;   // defensive: never publish -1
            }

            // publish sel to the serial engine (one writer)
            if (tid == 32) ((volatile int*)S.selq)[step] = sel;

            // advance worker state: poison owned slot
            {
                int dlt = sel - wtid;
                if (dlt >= 0 && (dlt & 255) == 0) ml[dlt >> 8] = -1;
            }
            cls = S.slbl[sel];
            cx = S.px[sel]; cy = S.py[sel]; cz = S.pz[sel];
        }
    }
    // warps 9..15 fall through directly to the join barrier

    __syncthreads();    // join serial + candidate engines (+ idle warps)

    const int nc = S.bnc;

    // ---------------- stable descending sort by count (bitonic, 4096 keys) -----
    unsigned* skey = reinterpret_cast<unsigned*>(S.px);
    for (int i = tid; i < 4096; i += NT) {
        unsigned key = 0;
        if (i < nc) key = ((unsigned)S.ccount[i] << 12) | (4095u - (unsigned)i);
        skey[i] = key;
    }
    for (int i = tid; i < N; i += NT) { S.remap[i] = i; S.keep[i] = 1; }
    __syncthreads();

    for (int k = 2; k <= 4096; k <<= 1) {
        for (int j = k >> 1; j > 0; j >>= 1) {
#pragma unroll
            for (int e = 0; e < 8; ++e) {
                int i = tid + e * NT;
                int ixj = i ^ j;
                if (ixj > i) {
                    unsigned a2 = skey[i], b2 = skey[ixj];
                    bool descBlock = ((i & k) == 0);
                    if (descBlock ? (a2 < b2) : (a2 > b2)) { skey[i] = b2; skey[ixj] = a2; }
                }
            }
            __syncthreads();
        }
    }
    for (int i = tid; i < N; i += NT)
        if (i < nc) S.order[i] = 4095 - (int)(skey[i] & 4095u);
    __syncthreads();

    // ---------------- group order-positions by cluster class ----------
    if (wid < 10) {
        int c = wid, total = 0;
        int limit = (nc + 31) & ~31;
        for (int s = lane; s < limit; s += 32) {
            bool mm = (s < nc) && (S.ccls[S.order[s]] == c);
            unsigned bal = __ballot_sync(FULLMASK, mm);
            total += __popc(bal);
        }
        if (lane == 0) S.clsCount[c] = total;
    }
    __syncthreads();
    if (tid == 0) {
        int acc = 0;
        for (int c = 0; c < 10; ++c) { S.clsBase[c] = acc; acc += S.clsCount[c]; }
        S.clsBase[10] = acc;
    }
    __syncthreads();
    if (wid < 10) {
        int c = wid;
        int pos = S.clsBase[c];
        int limit = (nc + 31) & ~31;
        for (int s = lane; s < limit; s += 32) {
            bool mm = (s < nc) && (S.ccls[S.order[s]] == c);
            unsigned bal = __ballot_sync(FULLMASK, mm);
            if (mm) {
                int off = __popc(bal & ((1u << lane) - 1u));
                S.items[pos + off] = s;
            }
            pos += __popc(bal);
        }
    }
    __syncthreads();

    // ---------------- merge: independent per-class sequential chains ----------
    if (wid < 10) {
        int c    = wid;
        int base = S.clsBase[c];
        int len  = S.clsBase[c + 1] - base;
        float r2c = S.ar2[c];
        for (int t = 0; t < len; ++t) {
            __syncwarp();
            int ipos = S.items[base + t];
            if (!S.keep[ipos]) continue;
            int idx = S.order[ipos];
            float ax = S.ccx[idx], ay = S.ccy[idx], az = S.ccz[idx];
            for (int s = t + 1 + lane; s < len; s += 32) {
                int jpos = S.items[base + s];
                if (S.keep[jpos]) {
                    int jidx = S.order[jpos];
                    float dd = norm3_xla(__fsub_rn(S.ccx[jidx], ax),
                                         __fsub_rn(S.ccy[jidx], ay),
                                         __fsub_rn(S.ccz[jidx], az));
                    if (dd < r2c) {
                        S.keep[jpos]  = 0;
                        S.remap[jidx] = idx;
                    }
                }
            }
        }
    }
    __syncthreads();

    // ---------------- output (float32) ----------------
    for (int i = tid; i < N; i += NT)
        out[i] = (float)S.remap[S.sdl[i]];
}

extern "C" void kernel_launch(void* const* d_in, const int* in_sizes, int n_in,
                              void* d_out, int out_size)
{
    const float* pts     = nullptr;
    const int*   lbls    = nullptr;
    const float* anchors = nullptr;
    for (int i = 0; i < n_in; ++i) {
        if      (in_sizes[i] == N * 3) pts     = (const float*)d_in[i];
        else if (in_sizes[i] == N)     lbls    = (const int*)  d_in[i];
        else if (in_sizes[i] == 30)    anchors = (const float*)d_in[i];
    }
    if (!pts)     pts     = (const float*)d_in[0];
    if (!lbls)    lbls    = (const int*)  d_in[1];
    if (!anchors) anchors = (const float*)d_in[2];

    float* out = (float*)d_out;
    (void)out_size;

    static bool attr_done = false;
    if (!attr_done) {
        cudaFuncSetAttribute(frustum_cluster_kernel,
                             cudaFuncAttributeMaxDynamicSharedMemorySize,
                             (int)sizeof(Smem));
        attr_done = true;
    }
    frustum_cluster_kernel<<<1, NT, sizeof(Smem)>>>(pts, lbls, anchors, out);
}